// round 12
// baseline (speedup 1.0000x reference)
#include <cuda_runtime.h>
#include <cuda_bf16.h>
#include <cuda_fp16.h>
#include <cstdint>

// Problem constants
#define B_    2048
#define F_    512
#define H_    64
#define K_    8
#define D_    128
#define ASR_  128
#define MM_   768
#define OUT_  256
#define ZPRE_ (ASR_ + MM_)          // 896
#define ZK_   (ZPRE_ + F_ * K_)     // 4992 (real contraction dim)
#define ZKP_  5120                  // padded (pad cols stay zero)
#define PROJ_IN_ (ASR_ + MM_ + F_ * D_)   // 66432
#define SPLITK 8
#define KSPLIT (ZKP_ / SPLITK)      // 640
#define BK    32
#define ITERS (KSPLIT / BK)         // 20

typedef unsigned long long ull;
typedef uint32_t u32;

// ---------- packed f32x2 helpers ----------
__device__ __forceinline__ ull pack2(float lo, float hi) {
    ull r; asm("mov.b64 %0, {%1, %2};" : "=l"(r) : "f"(lo), "f"(hi)); return r;
}
__device__ __forceinline__ void unpack2(ull v, float& lo, float& hi) {
    asm("mov.b64 {%0, %1}, %2;" : "=f"(lo), "=f"(hi) : "l"(v));
}
__device__ __forceinline__ void ffma2(ull& c, ull a, ull b) {
    asm("fma.rn.f32x2 %0, %1, %2, %0;" : "+l"(c) : "l"(a), "l"(b));
}

__device__ __forceinline__ u32 smem_u32(const void* p) {
    u32 a;
    asm("{ .reg .u64 t; cvta.to.shared.u64 t, %1; cvt.u32.u64 %0, t; }" : "=r"(a) : "l"(p));
    return a;
}

// fp16 split: 2 floats -> hi half2 + lo half2
__device__ __forceinline__ void split2h(float x, float y, u32& h, u32& l) {
    __half2 hb = __floats2half2_rn(x, y);
    float2 back = __half22float2(hb);
    __half2 lb = __floats2half2_rn(x - back.x, y - back.y);
    h = *(u32*)&hb;
    l = *(u32*)&lb;
}

// 8 floats -> 8 fp16
__device__ __forceinline__ uint4 pack8h(const float* s) {
    __half2 h0 = __floats2half2_rn(s[0], s[1]);
    __half2 h1 = __floats2half2_rn(s[2], s[3]);
    __half2 h2 = __floats2half2_rn(s[4], s[5]);
    __half2 h3 = __floats2half2_rn(s[6], s[7]);
    return make_uint4(*(u32*)&h0, *(u32*)&h1, *(u32*)&h2, *(u32*)&h3);
}

// mma.sync m16n8k16 fp16 -> fp32
__device__ __forceinline__ void mma_fp16(float* d, const u32* a, const u32* b) {
    asm volatile(
        "mma.sync.aligned.m16n8k16.row.col.f32.f16.f16.f32 "
        "{%0,%1,%2,%3}, {%4,%5,%6,%7}, {%8,%9}, {%0,%1,%2,%3};"
        : "+f"(d[0]), "+f"(d[1]), "+f"(d[2]), "+f"(d[3])
        : "r"(a[0]), "r"(a[1]), "r"(a[2]), "r"(a[3]), "r"(b[0]), "r"(b[1]));
}

__device__ __forceinline__ void ldsm_x4(u32* r, u32 addr) {
    asm volatile("ldmatrix.sync.aligned.m8n8.x4.shared.b16 {%0,%1,%2,%3}, [%4];"
        : "=r"(r[0]), "=r"(r[1]), "=r"(r[2]), "=r"(r[3]) : "r"(addr));
}
__device__ __forceinline__ void ldsm_x2(u32* r, u32 addr) {
    asm volatile("ldmatrix.sync.aligned.m8n8.x2.shared.b16 {%0,%1}, [%2];"
        : "=r"(r[0]), "=r"(r[1]) : "r"(addr));
}

#define CP_ASYNC(dst, src) \
    asm volatile("cp.async.cg.shared.global [%0], [%1], 16;" :: "r"(dst), "l"(src) : "memory")
#define CP_COMMIT() asm volatile("cp.async.commit_group;" ::: "memory")
#define CP_WAIT(N)  asm volatile("cp.async.wait_group %0;" :: "n"(N) : "memory")

// ---------- device scratch (zero-initialized; pad cols never written) ----------
__device__ float g_sT[(size_t)F_ * B_];            // stat^T sanitized (4 MB)
__device__ __half g_Zh[(size_t)B_ * ZKP_];         // 21 MB (A operand, fp16)
__device__ __half g_Bth[(size_t)OUT_ * ZKP_];      // 2.6 MB (B operand, fp16)
__device__ float g_CP[(size_t)SPLITK * B_ * OUT_];

// ============================================================
// Kernel T: sanitize + transpose stat[2048][512] -> g_sT[512][2048]
// ============================================================
__global__ __launch_bounds__(256) void kernelT(const float* __restrict__ stat)
{
    __shared__ float tile[32][33];
    const int tid = threadIdx.x;
    const int tx = tid & 31, ty = tid >> 5;
    const int f0 = (blockIdx.x & 15) * 32, b0 = (blockIdx.x >> 4) * 32;
#pragma unroll
    for (int i = 0; i < 4; i++) {
        float v = stat[(size_t)(b0 + ty + i * 8) * F_ + f0 + tx];
        tile[ty + i * 8][tx] = (v >= 0.f) ? v : 0.f;   // NaN & neg -> 0
    }
    __syncthreads();
#pragma unroll
    for (int i = 0; i < 4; i++)
        g_sT[(size_t)(f0 + ty + i * 8) * B_ + b0 + tx] = tile[tx][ty + i * 8];
}

// ============================================================
// Kernel Z1: asr -> Zh cols 0..127 (fp16). 128 blocks.
// ============================================================
__global__ __launch_bounds__(256) void kernelZ1(const float* __restrict__ asr)
{
    const int e = blockIdx.x * 256 + threadIdx.x;   // 32768 = 2048 * 16
    const int b = e >> 4, j8 = e & 15;
    const int col = j8 * 8;
    const float4* p = (const float4*)(asr + (size_t)b * ASR_ + col);
    float4 v0 = p[0], v1 = p[1];
    float s[8] = {v0.x, v0.y, v0.z, v0.w, v1.x, v1.y, v1.z, v1.w};
    *(uint4*)(g_Zh + (size_t)b * ZKP_ + col) = pack8h(s);
}

// ============================================================
// Kernel Z2: mm -> Zh cols 128..895 (fp16). 768 blocks.
// ============================================================
__global__ __launch_bounds__(256) void kernelZ2(const float* __restrict__ mmv)
{
    const int e = blockIdx.x * 256 + threadIdx.x;   // 196608 = 2048 * 96
    const int b = e / 96, j8 = e % 96;
    const int col = j8 * 8;
    const float4* p = (const float4*)(mmv + (size_t)b * MM_ + col);
    float4 v0 = p[0], v1 = p[1];
    float s[8] = {v0.x, v0.y, v0.z, v0.w, v1.x, v1.y, v1.z, v1.w};
    *(uint4*)(g_Zh + (size_t)b * ZKP_ + ASR_ + col) = pack8h(s);
}

// ============================================================
// Kernel AB (fused): interleaved A-work and B-work blocks.
//   blk < 1024:  even -> A (f = blk>>1), odd -> B M-build (f = blk>>1)
//   blk >= 1024: B copy of proj_w cols 0..895 (112 blocks)
// (code identical to R11 for clean attribution — this launch is
//  the 4th => captured by ncu this round)
// ============================================================
__global__ __launch_bounds__(256) void kernelAB(
    const float* __restrict__ w1, const float* __restrict__ b1,
    const float* __restrict__ w2, const float* __restrict__ b2,
    const float* __restrict__ tau,
    const float* __restrict__ emb, const float* __restrict__ pw)
{
    const int blk = blockIdx.x;
    const int tid = threadIdx.x;

    if (blk < 1024 && (blk & 1) == 0) {
        // ---------------- A: per-feature MLP + softmax ----------------
        __shared__ float w1s[H_], b1s[H_], b2s[K_], taus[K_];
        __shared__ ull   w2s[H_ * K_ / 2];
        const int f = blk >> 1;

        if (tid < H_) {
            const float* p = w1 + (size_t)f * 3 * H_;
            w1s[tid] = p[tid] + p[H_ + tid] + p[2 * H_ + tid];
            b1s[tid] = b1[(size_t)f * H_ + tid];
        } else if (tid < H_ + K_) {
            b2s[tid - H_] = b2[(size_t)f * K_ + tid - H_];
            taus[tid - H_] = tau[(size_t)f * K_ + tid - H_];
        }
        if (tid < 128) ((float4*)w2s)[tid] = ((const float4*)(w2 + (size_t)f * H_ * K_))[tid];
        __syncthreads();

        float x[8];
#pragma unroll
        for (int i = 0; i < 8; i++)
            x[i] = g_sT[(size_t)f * B_ + i * 256 + tid];

        ull acc[8][4];
#pragma unroll
        for (int i = 0; i < 8; i++)
#pragma unroll
            for (int k = 0; k < 4; k++) acc[i][k] = 0ull;

#pragma unroll 4
        for (int j = 0; j < H_; j++) {
            const float wj = w1s[j];
            const float bj = b1s[j];
            const ull u0 = w2s[j * 4 + 0];
            const ull u1 = w2s[j * 4 + 1];
            const ull u2 = w2s[j * 4 + 2];
            const ull u3 = w2s[j * 4 + 3];
#pragma unroll
            for (int i = 0; i < 8; i++) {
                float h = fmaf(x[i], wj, bj);
                h = fmaxf(h, 0.01f * h);
                ull h2 = pack2(h, h);
                ffma2(acc[i][0], h2, u0);
                ffma2(acc[i][1], h2, u1);
                ffma2(acc[i][2], h2, u2);
                ffma2(acc[i][3], h2, u3);
            }
        }

#pragma unroll
        for (int i = 0; i < 8; i++) {
            float s[8];
#pragma unroll
            for (int k = 0; k < 4; k++) unpack2(acc[i][k], s[2 * k], s[2 * k + 1]);
            float mx = -3.0e38f;
#pragma unroll
            for (int k = 0; k < K_; k++) {
                float pre = s[k] + b2s[k];
                pre = fmaxf(pre, 0.01f * pre);
                pre *= taus[k];
                s[k] = pre;
                mx = fmaxf(mx, pre);
            }
            float sum = 0.f;
#pragma unroll
            for (int k = 0; k < K_; k++) { s[k] = __expf(s[k] - mx); sum += s[k]; }
            const float inv = __frcp_rn(sum);
#pragma unroll
            for (int k = 0; k < K_; k++) s[k] *= inv;
            const size_t off = (size_t)(i * 256 + tid) * ZKP_ + ZPRE_ + f * K_;
            *(uint4*)(g_Zh + off) = pack8h(s);
        }
    } else if (blk < 1024) {
        // ---------------- B: M-build via fp16 split-2 MMA ----------------
        __shared__ float es[K_][D_];   // 4 KB raw emb for this f
        const int f = blk >> 1;
        ((float4*)es)[tid] = ((const float4*)(emb + (size_t)f * K_ * D_))[tid];
        __syncthreads();

        const int lane = tid & 31;
        const int w = tid >> 5;
        const int g = lane >> 2;      // 0..7
        const int tg = lane & 3;      // 0..3
        const int o0 = w * 32;        // 32 o-rows per warp

        u32 bh[8][2], bl[8][2];
#pragma unroll
        for (int c = 0; c < 8; c++) {
            const float* er = &es[g][c * 16];
            split2h(er[2 * tg],     er[2 * tg + 1], bh[c][0], bl[c][0]);
            split2h(er[2 * tg + 8], er[2 * tg + 9], bh[c][1], bl[c][1]);
        }

        float d0[4] = {0.f, 0.f, 0.f, 0.f};
        float d1[4] = {0.f, 0.f, 0.f, 0.f};

        const float* pwb = pw + ZPRE_ + (size_t)f * D_;
#pragma unroll
        for (int c = 0; c < 8; c++) {
            const int dc = c * 16;
#pragma unroll
            for (int mt = 0; mt < 2; mt++) {
                const float* r0 = pwb + (size_t)(o0 + mt * 16 + g) * PROJ_IN_ + dc + 2 * tg;
                const float* r1 = r0 + 8 * PROJ_IN_;
                float2 f0 = *(const float2*)(r0);
                float2 f1 = *(const float2*)(r1);
                float2 f2 = *(const float2*)(r0 + 8);
                float2 f3 = *(const float2*)(r1 + 8);
                u32 ah[4], al[4];
                split2h(f0.x, f0.y, ah[0], al[0]);
                split2h(f1.x, f1.y, ah[1], al[1]);
                split2h(f2.x, f2.y, ah[2], al[2]);
                split2h(f3.x, f3.y, ah[3], al[3]);
                float* dd = mt ? d1 : d0;
                mma_fp16(dd, ah, bh[c]);
                mma_fp16(dd, ah, bl[c]);
                mma_fp16(dd, al, bh[c]);
            }
        }

        const size_t cb = ZPRE_ + (size_t)f * K_ + 2 * tg;
#pragma unroll
        for (int mt = 0; mt < 2; mt++) {
            const float* dd = mt ? d1 : d0;
            const int ra = o0 + mt * 16 + g;
            __half2 h0 = __floats2half2_rn(dd[0], dd[1]);
            __half2 h1 = __floats2half2_rn(dd[2], dd[3]);
            *(u32*)(g_Bth + (size_t)ra * ZKP_ + cb)       = *(u32*)&h0;
            *(u32*)(g_Bth + (size_t)(ra + 8) * ZKP_ + cb) = *(u32*)&h1;
        }
    } else {
        // ---------------- B: copy proj_w cols 0..895 ----------------
        const int e = (blk - 1024) * 256 + tid;
        const int o = e / 112, j8 = e % 112;
        const int col = j8 * 8;
        const float4* p = (const float4*)(pw + (size_t)o * PROJ_IN_ + col);
        float4 v0 = p[0], v1 = p[1];
        float s[8] = {v0.x, v0.y, v0.z, v0.w, v1.x, v1.y, v1.z, v1.w};
        *(uint4*)(g_Bth + (size_t)o * ZKP_ + col) = pack8h(s);
    }
}

// ============================================================
// Kernel C: single-term fp16 mma.sync GEMM (C = Zh*Bh).
// BM=128 BN=128 BK=32, splitK=8 -> grid (16, 2, 8) = 256 CTAs.
// ============================================================
#define ROWB 80                        // 64B data + 16B pad (conflict-free ldsm)
#define MATB (128 * ROWB)              // 10240
#define STAGEB (2 * MATB)              // 20480: [A | B]
#define NSTAGE 4
#define SMEM_C_BYTES (NSTAGE * STAGEB) // 81920

__global__ __launch_bounds__(256, 2) void kernelC()
{
    extern __shared__ char smem[];
    const u32 smem_base = smem_u32(smem);
    const int tid = threadIdx.x;
    const int gm = blockIdx.x * 128;
    const int gn = blockIdx.y * 128;
    const int kbase = blockIdx.z * KSPLIT;

    const int lane = tid & 31;
    const int w = tid >> 5;
    const int g = lane >> 2;
    const int tg = lane & 3;
    const int m_off = (w & 3) * 32;
    const int n_off = (w >> 2) * 64;

    u32 aoff[2], boff[8];
#pragma unroll
    for (int i = 0; i < 2; i++)
        aoff[i] = (u32)((m_off + i * 16 + (lane & 15)) * ROWB + ((lane >> 4) << 4));
#pragma unroll
    for (int j = 0; j < 8; j++)
        boff[j] = (u32)((n_off + j * 8 + (lane & 7)) * ROWB + (((lane >> 3) & 1) << 4));

    float d[2][8][4];
#pragma unroll
    for (int i = 0; i < 2; i++)
#pragma unroll
        for (int j = 0; j < 8; j++)
#pragma unroll
            for (int c = 0; c < 4; c++) d[i][j][c] = 0.f;

#define FETCH(T, S)                                                                  \
    do {                                                                             \
        const int koff = kbase + (T) * BK;                                           \
        const u32 sb0 = smem_base + (S) * STAGEB;                                    \
        _Pragma("unroll")                                                            \
        for (int ci = 0; ci < 4; ci++) {                                             \
            int c = tid + ci * 256;                                                  \
            int idx = c & 511, row = idx >> 2, q = idx & 3;                          \
            const __half* src;                                                       \
            u32 dst;                                                                 \
            if (c < 512) {                                                           \
                src = g_Zh + (size_t)(gm + row) * ZKP_ + koff + q * 8;               \
                dst = sb0 + row * ROWB + q * 16;                                     \
            } else {                                                                 \
                src = g_Bth + (size_t)(gn + row) * ZKP_ + koff + q * 8;              \
                dst = sb0 + MATB + row * ROWB + q * 16;                              \
            }                                                                        \
            CP_ASYNC(dst, src);                                                      \
        }                                                                            \
    } while (0)

    FETCH(0, 0); CP_COMMIT();
    FETCH(1, 1); CP_COMMIT();
    FETCH(2, 2); CP_COMMIT();

#pragma unroll 1
    for (int t = 0; t < ITERS; t++) {
        CP_WAIT(2);
        __syncthreads();

        if (t + 3 < ITERS) FETCH(t + 3, (t + 3) & 3);
        CP_COMMIT();

        const u32 sb = smem_base + (t & 3) * STAGEB;

        u32 ah[2][2][4], bh[2][8][2];
#pragma unroll
        for (int s = 0; s < 2; s++) {
            const u32 kb = s * 32;
#pragma unroll
            for (int i = 0; i < 2; i++) ldsm_x4(ah[s][i], sb + aoff[i] + kb);
#pragma unroll
            for (int j = 0; j < 8; j++) ldsm_x2(bh[s][j], sb + MATB + boff[j] + kb);
        }
#pragma unroll
        for (int s = 0; s < 2; s++)
#pragma unroll
            for (int i = 0; i < 2; i++)
#pragma unroll
                for (int j = 0; j < 8; j++) mma_fp16(d[i][j], ah[s][i], bh[s][j]);
    }

    float* outp = g_CP + (size_t)blockIdx.z * (B_ * OUT_);
#pragma unroll
    for (int i = 0; i < 2; i++) {
        const int row = gm + m_off + 16 * i + g;
#pragma unroll
        for (int j = 0; j < 8; j++) {
            const int col = gn + n_off + 8 * j + 2 * tg;
            *(float2*)(outp + (size_t)row * OUT_ + col)       = make_float2(d[i][j][0], d[i][j][1]);
            *(float2*)(outp + (size_t)(row + 8) * OUT_ + col) = make_float2(d[i][j][2], d[i][j][3]);
        }
    }
#undef FETCH
}

// ============================================================
// Kernel D: out = relu(sum_z CP[z] + bias)
// ============================================================
__global__ __launch_bounds__(256) void kernelD(
    const float* __restrict__ pb, float* __restrict__ out)
{
    const int idx = blockIdx.x * 256 + threadIdx.x;
    float4 a = make_float4(0.f, 0.f, 0.f, 0.f);
#pragma unroll
    for (int z = 0; z < SPLITK; z++) {
        float4 v = ((const float4*)g_CP)[(size_t)z * (B_ * OUT_ / 4) + idx];
        a.x += v.x; a.y += v.y; a.z += v.z; a.w += v.w;
    }
    float4 bi = ((const float4*)pb)[idx & (OUT_ / 4 - 1)];
    float4 r;
    r.x = fmaxf(a.x + bi.x, 0.f);
    r.y = fmaxf(a.y + bi.y, 0.f);
    r.z = fmaxf(a.z + bi.z, 0.f);
    r.w = fmaxf(a.w + bi.w, 0.f);
    ((float4*)out)[idx] = r;
}

extern "C" void kernel_launch(void* const* d_in, const int* in_sizes, int n_in,
                              void* d_out, int out_size)
{
    const float* stat = (const float*)d_in[0];
    const float* asr  = (const float*)d_in[1];
    const float* mmv  = (const float*)d_in[2];
    const float* w1   = (const float*)d_in[3];
    const float* b1   = (const float*)d_in[4];
    const float* w2   = (const float*)d_in[5];
    const float* b2   = (const float*)d_in[6];
    const float* tau  = (const float*)d_in[7];
    const float* emb  = (const float*)d_in[8];
    const float* pw   = (const float*)d_in[9];
    const float* pb   = (const float*)d_in[10];
    float* out = (float*)d_out;

    static int smem_set = 0;
    if (!smem_set) {
        cudaFuncSetAttribute(kernelC, cudaFuncAttributeMaxDynamicSharedMemorySize, SMEM_C_BYTES);
        smem_set = 1;
    }

    kernelT<<<1024, 256>>>(stat);                                 // 1st
    kernelZ1<<<128, 256>>>(asr);                                  // 2nd
    kernelZ2<<<768, 256>>>(mmv);                                  // 3rd
    kernelAB<<<1024 + 112, 256>>>(w1, b1, w2, b2, tau, emb, pw);  // 4th <- profiled
    dim3 gc(B_ / 128, OUT_ / 128, SPLITK);
    kernelC<<<gc, 256, SMEM_C_BYTES>>>();                         // 5th
    kernelD<<<(B_ * OUT_ / 4) / 256, 256>>>(pb, out);             // 6th
}

// round 13
// speedup vs baseline: 1.0922x; 1.0922x over previous
#include <cuda_runtime.h>
#include <cuda_bf16.h>
#include <cuda_fp16.h>
#include <cstdint>

// Problem constants
#define B_    2048
#define F_    512
#define H_    64
#define K_    8
#define D_    128
#define ASR_  128
#define MM_   768
#define OUT_  256
#define ZPRE_ (ASR_ + MM_)          // 896
#define ZK_   (ZPRE_ + F_ * K_)     // 4992 (real contraction dim)
#define ZKP_  5120                  // padded (pad cols stay zero)
#define PROJ_IN_ (ASR_ + MM_ + F_ * D_)   // 66432
#define SPLITK 8
#define KSPLIT (ZKP_ / SPLITK)      // 640
#define BK    32
#define ITERS (KSPLIT / BK)         // 20

typedef unsigned long long ull;
typedef uint32_t u32;

// ---------- packed f32x2 helpers ----------
__device__ __forceinline__ ull pack2(float lo, float hi) {
    ull r; asm("mov.b64 %0, {%1, %2};" : "=l"(r) : "f"(lo), "f"(hi)); return r;
}
__device__ __forceinline__ void unpack2(ull v, float& lo, float& hi) {
    asm("mov.b64 {%0, %1}, %2;" : "=f"(lo), "=f"(hi) : "l"(v));
}
__device__ __forceinline__ void ffma2(ull& c, ull a, ull b) {
    asm("fma.rn.f32x2 %0, %1, %2, %0;" : "+l"(c) : "l"(a), "l"(b));
}

__device__ __forceinline__ u32 smem_u32(const void* p) {
    u32 a;
    asm("{ .reg .u64 t; cvta.to.shared.u64 t, %1; cvt.u32.u64 %0, t; }" : "=r"(a) : "l"(p));
    return a;
}

// fp16 split: 2 floats -> hi half2 + lo half2
__device__ __forceinline__ void split2h(float x, float y, u32& h, u32& l) {
    __half2 hb = __floats2half2_rn(x, y);
    float2 back = __half22float2(hb);
    __half2 lb = __floats2half2_rn(x - back.x, y - back.y);
    h = *(u32*)&hb;
    l = *(u32*)&lb;
}

// 8 floats -> 8 fp16
__device__ __forceinline__ uint4 pack8h(const float* s) {
    __half2 h0 = __floats2half2_rn(s[0], s[1]);
    __half2 h1 = __floats2half2_rn(s[2], s[3]);
    __half2 h2 = __floats2half2_rn(s[4], s[5]);
    __half2 h3 = __floats2half2_rn(s[6], s[7]);
    return make_uint4(*(u32*)&h0, *(u32*)&h1, *(u32*)&h2, *(u32*)&h3);
}

// mma.sync m16n8k16 fp16 -> fp32
__device__ __forceinline__ void mma_fp16(float* d, const u32* a, const u32* b) {
    asm volatile(
        "mma.sync.aligned.m16n8k16.row.col.f32.f16.f16.f32 "
        "{%0,%1,%2,%3}, {%4,%5,%6,%7}, {%8,%9}, {%0,%1,%2,%3};"
        : "+f"(d[0]), "+f"(d[1]), "+f"(d[2]), "+f"(d[3])
        : "r"(a[0]), "r"(a[1]), "r"(a[2]), "r"(a[3]), "r"(b[0]), "r"(b[1]));
}

__device__ __forceinline__ void ldsm_x4(u32* r, u32 addr) {
    asm volatile("ldmatrix.sync.aligned.m8n8.x4.shared.b16 {%0,%1,%2,%3}, [%4];"
        : "=r"(r[0]), "=r"(r[1]), "=r"(r[2]), "=r"(r[3]) : "r"(addr));
}
__device__ __forceinline__ void ldsm_x2(u32* r, u32 addr) {
    asm volatile("ldmatrix.sync.aligned.m8n8.x2.shared.b16 {%0,%1}, [%2];"
        : "=r"(r[0]), "=r"(r[1]) : "r"(addr));
}

#define CP_ASYNC(dst, src) \
    asm volatile("cp.async.cg.shared.global [%0], [%1], 16;" :: "r"(dst), "l"(src) : "memory")
#define CP_COMMIT() asm volatile("cp.async.commit_group;" ::: "memory")
#define CP_WAIT(N)  asm volatile("cp.async.wait_group %0;" :: "n"(N) : "memory")

// ---------- device scratch (zero-initialized; pad cols never written) ----------
__device__ float g_sT[(size_t)F_ * B_];            // stat^T sanitized (4 MB)
__device__ __half g_Zh[(size_t)B_ * ZKP_];         // 21 MB (A operand, fp16)
__device__ __half g_Bth[(size_t)OUT_ * ZKP_];      // 2.6 MB (B operand, fp16)
__device__ float g_CP[(size_t)SPLITK * B_ * OUT_];

// ============================================================
// Kernel T: sanitize + transpose stat[2048][512] -> g_sT[512][2048]
// ============================================================
__global__ __launch_bounds__(256) void kernelT(const float* __restrict__ stat)
{
    __shared__ float tile[32][33];
    const int tid = threadIdx.x;
    const int tx = tid & 31, ty = tid >> 5;
    const int f0 = (blockIdx.x & 15) * 32, b0 = (blockIdx.x >> 4) * 32;
#pragma unroll
    for (int i = 0; i < 4; i++) {
        float v = stat[(size_t)(b0 + ty + i * 8) * F_ + f0 + tx];
        tile[ty + i * 8][tx] = (v >= 0.f) ? v : 0.f;   // NaN & neg -> 0
    }
    __syncthreads();
#pragma unroll
    for (int i = 0; i < 4; i++)
        g_sT[(size_t)(f0 + ty + i * 8) * B_ + b0 + tx] = tile[tx][ty + i * 8];
}

// ============================================================
// Kernel Z1: asr -> Zh cols 0..127 (fp16). 128 blocks.
// ============================================================
__global__ __launch_bounds__(256) void kernelZ1(const float* __restrict__ asr)
{
    const int e = blockIdx.x * 256 + threadIdx.x;   // 32768 = 2048 * 16
    const int b = e >> 4, j8 = e & 15;
    const int col = j8 * 8;
    const float4* p = (const float4*)(asr + (size_t)b * ASR_ + col);
    float4 v0 = p[0], v1 = p[1];
    float s[8] = {v0.x, v0.y, v0.z, v0.w, v1.x, v1.y, v1.z, v1.w};
    *(uint4*)(g_Zh + (size_t)b * ZKP_ + col) = pack8h(s);
}

// ============================================================
// Kernel Z2: mm -> Zh cols 128..895 (fp16). 768 blocks.
// ============================================================
__global__ __launch_bounds__(256) void kernelZ2(const float* __restrict__ mmv)
{
    const int e = blockIdx.x * 256 + threadIdx.x;   // 196608 = 2048 * 96
    const int b = e / 96, j8 = e % 96;
    const int col = j8 * 8;
    const float4* p = (const float4*)(mmv + (size_t)b * MM_ + col);
    float4 v0 = p[0], v1 = p[1];
    float s[8] = {v0.x, v0.y, v0.z, v0.w, v1.x, v1.y, v1.z, v1.w};
    *(uint4*)(g_Zh + (size_t)b * ZKP_ + ASR_ + col) = pack8h(s);
}

// ============================================================
// Kernel AB (fused, v2): A split into 2 blocks/feature (4 rows per
// thread, acc 32 regs) -> lower reg pressure -> 3 CTAs/SM.
// Interleave 2A:1B: blk<1536: trip=blk/3, r=blk%3;
//   r<2 -> A (f=trip, rows trip-half r), r==2 -> B M-build (f=trip)
// blk>=1536: B copy of proj_w cols 0..895 (112 blocks)
// ============================================================
__global__ __launch_bounds__(256) void kernelAB(
    const float* __restrict__ w1, const float* __restrict__ b1,
    const float* __restrict__ w2, const float* __restrict__ b2,
    const float* __restrict__ tau,
    const float* __restrict__ emb, const float* __restrict__ pw)
{
    const int blk = blockIdx.x;
    const int tid = threadIdx.x;
    const int trip = blk / 3;
    const int r = blk - trip * 3;

    if (blk < 1536 && r < 2) {
        // ---------------- A: per-feature MLP + softmax (half batch) ----------------
        __shared__ float w1s[H_], b1s[H_], b2s[K_], taus[K_];
        __shared__ ull   w2s[H_ * K_ / 2];
        const int f = trip;
        const int rowbase = r * 1024;

        if (tid < H_) {
            const float* p = w1 + (size_t)f * 3 * H_;
            w1s[tid] = p[tid] + p[H_ + tid] + p[2 * H_ + tid];
            b1s[tid] = b1[(size_t)f * H_ + tid];
        } else if (tid < H_ + K_) {
            b2s[tid - H_] = b2[(size_t)f * K_ + tid - H_];
            taus[tid - H_] = tau[(size_t)f * K_ + tid - H_];
        }
        if (tid < 128) ((float4*)w2s)[tid] = ((const float4*)(w2 + (size_t)f * H_ * K_))[tid];
        __syncthreads();

        float x[4];
#pragma unroll
        for (int i = 0; i < 4; i++)
            x[i] = g_sT[(size_t)f * B_ + rowbase + i * 256 + tid];

        ull acc[4][4];
#pragma unroll
        for (int i = 0; i < 4; i++)
#pragma unroll
            for (int k = 0; k < 4; k++) acc[i][k] = 0ull;

#pragma unroll 4
        for (int j = 0; j < H_; j++) {
            const float wj = w1s[j];
            const float bj = b1s[j];
            const ull u0 = w2s[j * 4 + 0];
            const ull u1 = w2s[j * 4 + 1];
            const ull u2 = w2s[j * 4 + 2];
            const ull u3 = w2s[j * 4 + 3];
#pragma unroll
            for (int i = 0; i < 4; i++) {
                float h = fmaf(x[i], wj, bj);
                h = fmaxf(h, 0.01f * h);
                ull h2 = pack2(h, h);
                ffma2(acc[i][0], h2, u0);
                ffma2(acc[i][1], h2, u1);
                ffma2(acc[i][2], h2, u2);
                ffma2(acc[i][3], h2, u3);
            }
        }

#pragma unroll
        for (int i = 0; i < 4; i++) {
            float s[8];
#pragma unroll
            for (int k = 0; k < 4; k++) unpack2(acc[i][k], s[2 * k], s[2 * k + 1]);
            float mx = -3.0e38f;
#pragma unroll
            for (int k = 0; k < K_; k++) {
                float pre = s[k] + b2s[k];
                pre = fmaxf(pre, 0.01f * pre);
                pre *= taus[k];
                s[k] = pre;
                mx = fmaxf(mx, pre);
            }
            float sum = 0.f;
#pragma unroll
            for (int k = 0; k < K_; k++) { s[k] = __expf(s[k] - mx); sum += s[k]; }
            const float inv = __frcp_rn(sum);
#pragma unroll
            for (int k = 0; k < K_; k++) s[k] *= inv;
            const size_t off = (size_t)(rowbase + i * 256 + tid) * ZKP_ + ZPRE_ + f * K_;
            *(uint4*)(g_Zh + off) = pack8h(s);
        }
    } else if (blk < 1536) {
        // ---------------- B: M-build via fp16 split-2 MMA ----------------
        __shared__ float es[K_][D_];   // 4 KB raw emb for this f
        const int f = trip;
        ((float4*)es)[tid] = ((const float4*)(emb + (size_t)f * K_ * D_))[tid];
        __syncthreads();

        const int lane = tid & 31;
        const int w = tid >> 5;
        const int g = lane >> 2;      // 0..7
        const int tg = lane & 3;      // 0..3
        const int o0 = w * 32;        // 32 o-rows per warp

        u32 bh[8][2], bl[8][2];
#pragma unroll
        for (int c = 0; c < 8; c++) {
            const float* er = &es[g][c * 16];
            split2h(er[2 * tg],     er[2 * tg + 1], bh[c][0], bl[c][0]);
            split2h(er[2 * tg + 8], er[2 * tg + 9], bh[c][1], bl[c][1]);
        }

        float d0[4] = {0.f, 0.f, 0.f, 0.f};
        float d1[4] = {0.f, 0.f, 0.f, 0.f};

        const float* pwb = pw + ZPRE_ + (size_t)f * D_;
#pragma unroll
        for (int c = 0; c < 8; c++) {
            const int dc = c * 16;
#pragma unroll
            for (int mt = 0; mt < 2; mt++) {
                const float* r0 = pwb + (size_t)(o0 + mt * 16 + g) * PROJ_IN_ + dc + 2 * tg;
                const float* r1 = r0 + 8 * PROJ_IN_;
                float2 f0 = *(const float2*)(r0);
                float2 f1 = *(const float2*)(r1);
                float2 f2 = *(const float2*)(r0 + 8);
                float2 f3 = *(const float2*)(r1 + 8);
                u32 ah[4], al[4];
                split2h(f0.x, f0.y, ah[0], al[0]);
                split2h(f1.x, f1.y, ah[1], al[1]);
                split2h(f2.x, f2.y, ah[2], al[2]);
                split2h(f3.x, f3.y, ah[3], al[3]);
                float* dd = mt ? d1 : d0;
                mma_fp16(dd, ah, bh[c]);
                mma_fp16(dd, ah, bl[c]);
                mma_fp16(dd, al, bh[c]);
            }
        }

        const size_t cb = ZPRE_ + (size_t)f * K_ + 2 * tg;
#pragma unroll
        for (int mt = 0; mt < 2; mt++) {
            const float* dd = mt ? d1 : d0;
            const int ra = o0 + mt * 16 + g;
            __half2 h0 = __floats2half2_rn(dd[0], dd[1]);
            __half2 h1 = __floats2half2_rn(dd[2], dd[3]);
            *(u32*)(g_Bth + (size_t)ra * ZKP_ + cb)       = *(u32*)&h0;
            *(u32*)(g_Bth + (size_t)(ra + 8) * ZKP_ + cb) = *(u32*)&h1;
        }
    } else {
        // ---------------- B: copy proj_w cols 0..895 ----------------
        const int e = (blk - 1536) * 256 + tid;
        const int o = e / 112, j8 = e % 112;
        const int col = j8 * 8;
        const float4* p = (const float4*)(pw + (size_t)o * PROJ_IN_ + col);
        float4 v0 = p[0], v1 = p[1];
        float s[8] = {v0.x, v0.y, v0.z, v0.w, v1.x, v1.y, v1.z, v1.w};
        *(uint4*)(g_Bth + (size_t)o * ZKP_ + col) = pack8h(s);
    }
}

// ============================================================
// Kernel C: single-term fp16 mma.sync GEMM (C = Zh*Bh).
// BM=128 BN=128 BK=32, splitK=8 -> grid (16, 2, 8) = 256 CTAs.
// ============================================================
#define ROWB 80                        // 64B data + 16B pad (conflict-free ldsm)
#define MATB (128 * ROWB)              // 10240
#define STAGEB (2 * MATB)              // 20480: [A | B]
#define NSTAGE 4
#define SMEM_C_BYTES (NSTAGE * STAGEB) // 81920

__global__ __launch_bounds__(256, 2) void kernelC()
{
    extern __shared__ char smem[];
    const u32 smem_base = smem_u32(smem);
    const int tid = threadIdx.x;
    const int gm = blockIdx.x * 128;
    const int gn = blockIdx.y * 128;
    const int kbase = blockIdx.z * KSPLIT;

    const int lane = tid & 31;
    const int w = tid >> 5;
    const int g = lane >> 2;
    const int tg = lane & 3;
    const int m_off = (w & 3) * 32;
    const int n_off = (w >> 2) * 64;

    u32 aoff[2], boff[8];
#pragma unroll
    for (int i = 0; i < 2; i++)
        aoff[i] = (u32)((m_off + i * 16 + (lane & 15)) * ROWB + ((lane >> 4) << 4));
#pragma unroll
    for (int j = 0; j < 8; j++)
        boff[j] = (u32)((n_off + j * 8 + (lane & 7)) * ROWB + (((lane >> 3) & 1) << 4));

    float d[2][8][4];
#pragma unroll
    for (int i = 0; i < 2; i++)
#pragma unroll
        for (int j = 0; j < 8; j++)
#pragma unroll
            for (int c = 0; c < 4; c++) d[i][j][c] = 0.f;

#define FETCH(T, S)                                                                  \
    do {                                                                             \
        const int koff = kbase + (T) * BK;                                           \
        const u32 sb0 = smem_base + (S) * STAGEB;                                    \
        _Pragma("unroll")                                                            \
        for (int ci = 0; ci < 4; ci++) {                                             \
            int c = tid + ci * 256;                                                  \
            int idx = c & 511, row = idx >> 2, q = idx & 3;                          \
            const __half* src;                                                       \
            u32 dst;                                                                 \
            if (c < 512) {                                                           \
                src = g_Zh + (size_t)(gm + row) * ZKP_ + koff + q * 8;               \
                dst = sb0 + row * ROWB + q * 16;                                     \
            } else {                                                                 \
                src = g_Bth + (size_t)(gn + row) * ZKP_ + koff + q * 8;              \
                dst = sb0 + MATB + row * ROWB + q * 16;                              \
            }                                                                        \
            CP_ASYNC(dst, src);                                                      \
        }                                                                            \
    } while (0)

    FETCH(0, 0); CP_COMMIT();
    FETCH(1, 1); CP_COMMIT();
    FETCH(2, 2); CP_COMMIT();

#pragma unroll 1
    for (int t = 0; t < ITERS; t++) {
        CP_WAIT(2);
        __syncthreads();

        if (t + 3 < ITERS) FETCH(t + 3, (t + 3) & 3);
        CP_COMMIT();

        const u32 sb = smem_base + (t & 3) * STAGEB;

        u32 ah[2][2][4], bh[2][8][2];
#pragma unroll
        for (int s = 0; s < 2; s++) {
            const u32 kb = s * 32;
#pragma unroll
            for (int i = 0; i < 2; i++) ldsm_x4(ah[s][i], sb + aoff[i] + kb);
#pragma unroll
            for (int j = 0; j < 8; j++) ldsm_x2(bh[s][j], sb + MATB + boff[j] + kb);
        }
#pragma unroll
        for (int s = 0; s < 2; s++)
#pragma unroll
            for (int i = 0; i < 2; i++)
#pragma unroll
                for (int j = 0; j < 8; j++) mma_fp16(d[i][j], ah[s][i], bh[s][j]);
    }

    float* outp = g_CP + (size_t)blockIdx.z * (B_ * OUT_);
#pragma unroll
    for (int i = 0; i < 2; i++) {
        const int row = gm + m_off + 16 * i + g;
#pragma unroll
        for (int j = 0; j < 8; j++) {
            const int col = gn + n_off + 8 * j + 2 * tg;
            *(float2*)(outp + (size_t)row * OUT_ + col)       = make_float2(d[i][j][0], d[i][j][1]);
            *(float2*)(outp + (size_t)(row + 8) * OUT_ + col) = make_float2(d[i][j][2], d[i][j][3]);
        }
    }
#undef FETCH
}

// ============================================================
// Kernel D: out = relu(sum_z CP[z] + bias)
// ============================================================
__global__ __launch_bounds__(256) void kernelD(
    const float* __restrict__ pb, float* __restrict__ out)
{
    const int idx = blockIdx.x * 256 + threadIdx.x;
    float4 a = make_float4(0.f, 0.f, 0.f, 0.f);
#pragma unroll
    for (int z = 0; z < SPLITK; z++) {
        float4 v = ((const float4*)g_CP)[(size_t)z * (B_ * OUT_ / 4) + idx];
        a.x += v.x; a.y += v.y; a.z += v.z; a.w += v.w;
    }
    float4 bi = ((const float4*)pb)[idx & (OUT_ / 4 - 1)];
    float4 r;
    r.x = fmaxf(a.x + bi.x, 0.f);
    r.y = fmaxf(a.y + bi.y, 0.f);
    r.z = fmaxf(a.z + bi.z, 0.f);
    r.w = fmaxf(a.w + bi.w, 0.f);
    ((float4*)out)[idx] = r;
}

extern "C" void kernel_launch(void* const* d_in, const int* in_sizes, int n_in,
                              void* d_out, int out_size)
{
    const float* stat = (const float*)d_in[0];
    const float* asr  = (const float*)d_in[1];
    const float* mmv  = (const float*)d_in[2];
    const float* w1   = (const float*)d_in[3];
    const float* b1   = (const float*)d_in[4];
    const float* w2   = (const float*)d_in[5];
    const float* b2   = (const float*)d_in[6];
    const float* tau  = (const float*)d_in[7];
    const float* emb  = (const float*)d_in[8];
    const float* pw   = (const float*)d_in[9];
    const float* pb   = (const float*)d_in[10];
    float* out = (float*)d_out;

    static int smem_set = 0;
    if (!smem_set) {
        cudaFuncSetAttribute(kernelC, cudaFuncAttributeMaxDynamicSharedMemorySize, SMEM_C_BYTES);
        smem_set = 1;
    }

    kernelT<<<1024, 256>>>(stat);                                 // 1st
    kernelZ1<<<128, 256>>>(asr);                                  // 2nd
    kernelZ2<<<768, 256>>>(mmv);                                  // 3rd
    kernelAB<<<1536 + 112, 256>>>(w1, b1, w2, b2, tau, emb, pw);  // 4th <- profiled
    dim3 gc(B_ / 128, OUT_ / 128, SPLITK);
    kernelC<<<gc, 256, SMEM_C_BYTES>>>();                         // 5th
    kernelD<<<(B_ * OUT_ / 4) / 256, 256>>>(pb, out);             // 6th
}

// round 14
// speedup vs baseline: 1.1788x; 1.0793x over previous
#include <cuda_runtime.h>
#include <cuda_bf16.h>
#include <cuda_fp16.h>
#include <cstdint>

// Problem constants
#define B_    2048
#define F_    512
#define H_    64
#define K_    8
#define D_    128
#define ASR_  128
#define MM_   768
#define OUT_  256
#define ZPRE_ (ASR_ + MM_)          // 896
#define ZK_   (ZPRE_ + F_ * K_)     // 4992 (real contraction dim)
#define ZKP_  5120                  // padded (pad cols stay zero)
#define PROJ_IN_ (ASR_ + MM_ + F_ * D_)   // 66432
#define SPLITK 8
#define KSPLIT (ZKP_ / SPLITK)      // 640
#define BK    32
#define ITERS (KSPLIT / BK)         // 20

typedef unsigned long long ull;
typedef uint32_t u32;

__device__ __forceinline__ u32 smem_u32(const void* p) {
    u32 a;
    asm("{ .reg .u64 t; cvta.to.shared.u64 t, %1; cvt.u32.u64 %0, t; }" : "=r"(a) : "l"(p));
    return a;
}

// fp16 split: 2 floats -> hi half2 + lo half2
__device__ __forceinline__ void split2h(float x, float y, u32& h, u32& l) {
    __half2 hb = __floats2half2_rn(x, y);
    float2 back = __half22float2(hb);
    __half2 lb = __floats2half2_rn(x - back.x, y - back.y);
    h = *(u32*)&hb;
    l = *(u32*)&lb;
}

// 8 floats -> 8 fp16
__device__ __forceinline__ uint4 pack8h(const float* s) {
    __half2 h0 = __floats2half2_rn(s[0], s[1]);
    __half2 h1 = __floats2half2_rn(s[2], s[3]);
    __half2 h2 = __floats2half2_rn(s[4], s[5]);
    __half2 h3 = __floats2half2_rn(s[6], s[7]);
    return make_uint4(*(u32*)&h0, *(u32*)&h1, *(u32*)&h2, *(u32*)&h3);
}

// mma.sync m16n8k16 fp16 -> fp32
__device__ __forceinline__ void mma_fp16(float* d, const u32* a, const u32* b) {
    asm volatile(
        "mma.sync.aligned.m16n8k16.row.col.f32.f16.f16.f32 "
        "{%0,%1,%2,%3}, {%4,%5,%6,%7}, {%8,%9}, {%0,%1,%2,%3};"
        : "+f"(d[0]), "+f"(d[1]), "+f"(d[2]), "+f"(d[3])
        : "r"(a[0]), "r"(a[1]), "r"(a[2]), "r"(a[3]), "r"(b[0]), "r"(b[1]));
}

__device__ __forceinline__ void ldsm_x4(u32* r, u32 addr) {
    asm volatile("ldmatrix.sync.aligned.m8n8.x4.shared.b16 {%0,%1,%2,%3}, [%4];"
        : "=r"(r[0]), "=r"(r[1]), "=r"(r[2]), "=r"(r[3]) : "r"(addr));
}
__device__ __forceinline__ void ldsm_x2(u32* r, u32 addr) {
    asm volatile("ldmatrix.sync.aligned.m8n8.x2.shared.b16 {%0,%1}, [%2];"
        : "=r"(r[0]), "=r"(r[1]) : "r"(addr));
}

#define CP_ASYNC(dst, src) \
    asm volatile("cp.async.cg.shared.global [%0], [%1], 16;" :: "r"(dst), "l"(src) : "memory")
#define CP_COMMIT() asm volatile("cp.async.commit_group;" ::: "memory")
#define CP_WAIT(N)  asm volatile("cp.async.wait_group %0;" :: "n"(N) : "memory")

// ---------- device scratch (zero-initialized; pad cols never written) ----------
__device__ float g_sT[(size_t)F_ * B_];            // stat^T sanitized (4 MB)
__device__ __half g_Zh[(size_t)B_ * ZKP_];         // 21 MB (A operand, fp16)
__device__ __half g_Bth[(size_t)OUT_ * ZKP_];      // 2.6 MB (B operand, fp16)
__device__ float g_CP[(size_t)SPLITK * B_ * OUT_];

// ============================================================
// Kernel T: sanitize + transpose stat[2048][512] -> g_sT[512][2048]
// ============================================================
__global__ __launch_bounds__(256) void kernelT(const float* __restrict__ stat)
{
    __shared__ float tile[32][33];
    const int tid = threadIdx.x;
    const int tx = tid & 31, ty = tid >> 5;
    const int f0 = (blockIdx.x & 15) * 32, b0 = (blockIdx.x >> 4) * 32;
#pragma unroll
    for (int i = 0; i < 4; i++) {
        float v = stat[(size_t)(b0 + ty + i * 8) * F_ + f0 + tx];
        tile[ty + i * 8][tx] = (v >= 0.f) ? v : 0.f;   // NaN & neg -> 0
    }
    __syncthreads();
#pragma unroll
    for (int i = 0; i < 4; i++)
        g_sT[(size_t)(f0 + ty + i * 8) * B_ + b0 + tx] = tile[tx][ty + i * 8];
}

// ============================================================
// Kernel Z1: asr -> Zh cols 0..127 (fp16). 128 blocks.
// ============================================================
__global__ __launch_bounds__(256) void kernelZ1(const float* __restrict__ asr)
{
    const int e = blockIdx.x * 256 + threadIdx.x;   // 32768 = 2048 * 16
    const int b = e >> 4, j8 = e & 15;
    const int col = j8 * 8;
    const float4* p = (const float4*)(asr + (size_t)b * ASR_ + col);
    float4 v0 = p[0], v1 = p[1];
    float s[8] = {v0.x, v0.y, v0.z, v0.w, v1.x, v1.y, v1.z, v1.w};
    *(uint4*)(g_Zh + (size_t)b * ZKP_ + col) = pack8h(s);
}

// ============================================================
// Kernel Z2: mm -> Zh cols 128..895 (fp16). 768 blocks.
// ============================================================
__global__ __launch_bounds__(256) void kernelZ2(const float* __restrict__ mmv)
{
    const int e = blockIdx.x * 256 + threadIdx.x;   // 196608 = 2048 * 96
    const int b = e / 96, j8 = e % 96;
    const int col = j8 * 8;
    const float4* p = (const float4*)(mmv + (size_t)b * MM_ + col);
    float4 v0 = p[0], v1 = p[1];
    float s[8] = {v0.x, v0.y, v0.z, v0.w, v1.x, v1.y, v1.z, v1.w};
    *(uint4*)(g_Zh + (size_t)b * ZKP_ + ASR_ + col) = pack8h(s);
}

// ============================================================
// Kernel AB (fused, v3): A via piecewise-linear collapse.
//   leaky(v) = 0.505 v + 0.495 |v|  =>
//   s_k(x) = c0_k + c1_k x + sum_j a_jk |x - r_j|
// Per f: sort breakpoints, prefix-scan -> tab[m][k] = (A,B) with
// s_k = A + B x on interval m. Main phase: binary search + 8 fma.
//   blk < 1024: even -> A (f=blk>>1), odd -> B M-build (f=blk>>1)
//   blk >= 1024: B copy of proj_w cols 0..895 (112 blocks)
// ============================================================
struct SmemA {
    float rawA[64][8];     // a_jk
    float rawAR[64][8];    // a_jk * r_j
    float rawC1[64][8];
    float rawC0[64][8];
    float srtA[64][8];
    float srtAR[64][8];
    float R[128];          // sorted breakpoints, padded with +INF
    float tab[65][16];     // {A0,B0,A1,B1,...}
    float taus[8];
    float rtmp[64];
};
union SmemAB {
    SmemA a;
    float es[K_][D_];
};

__global__ __launch_bounds__(256) void kernelAB(
    const float* __restrict__ w1, const float* __restrict__ b1,
    const float* __restrict__ w2, const float* __restrict__ b2,
    const float* __restrict__ tau,
    const float* __restrict__ emb, const float* __restrict__ pw)
{
    __shared__ SmemAB smu;
    const int blk = blockIdx.x;
    const int tid = threadIdx.x;

    if (blk < 1024 && (blk & 1) == 0) {
        // ---------------- A: piecewise-linear MLP + softmax ----------------
        SmemA& sm = smu.a;
        const int f = blk >> 1;

        // phase 1: per-j coefficients
        if (tid < 64) {
            const int j = tid;
            const float* p = w1 + (size_t)f * 3 * H_;
            float w1s = p[j] + p[H_ + j] + p[2 * H_ + j];
            float b1v = b1[(size_t)f * H_ + j];
            float aw = fabsf(w1s);
            bool ok = aw > 1e-20f;
            float r = ok ? (-b1v / w1s) : 0.f;
            sm.rtmp[j] = r;
            const float* w2r = w2 + (size_t)f * H_ * K_ + j * K_;
#pragma unroll
            for (int k = 0; k < K_; k++) {
                float w2v = w2r[k];
                float a = ok ? (0.495f * aw * w2v) : 0.f;
                sm.rawA[j][k] = a;
                sm.rawAR[j][k] = a * r;
                sm.rawC1[j][k] = 0.505f * w1s * w2v;
                sm.rawC0[j][k] = 0.505f * b1v * w2v + (ok ? 0.f : 0.495f * fabsf(b1v) * w2v);
            }
        }
        if (tid >= 128 && tid < 136) sm.taus[tid - 128] = tau[(size_t)f * K_ + tid - 128];
        __syncthreads();

        // phase 2: rank + scatter to sorted order
        if (tid < 64) {
            const int j = tid;
            float r = sm.rtmp[j];
            int rank = 0;
#pragma unroll 8
            for (int i = 0; i < 64; i++) {
                float ri = sm.rtmp[i];
                rank += (ri < r) || (ri == r && i < j);
            }
            sm.R[rank] = r;
#pragma unroll
            for (int k = 0; k < K_; k++) {
                sm.srtA[rank][k]  = sm.rawA[j][k];
                sm.srtAR[rank][k] = sm.rawAR[j][k];
            }
        }
        if (tid >= 64 && tid < 128) sm.R[tid] = 3.0e38f;   // pad
        __syncthreads();

        // phase 3: warp w handles k=w; scan + table build
        const int w = tid >> 5, lane = tid & 31;
        if (w < 8) {
            const int k = w;
            float a0 = sm.srtA[2 * lane][k],  a1 = sm.srtA[2 * lane + 1][k];
            float r0 = sm.srtAR[2 * lane][k], r1 = sm.srtAR[2 * lane + 1][k];
            float pa = a0 + a1, pr = r0 + r1;
#pragma unroll
            for (int off = 1; off < 32; off <<= 1) {
                float ta = __shfl_up_sync(0xffffffffu, pa, off);
                float tr = __shfl_up_sync(0xffffffffu, pr, off);
                if (lane >= off) { pa += ta; pr += tr; }
            }
            float Sa = __shfl_sync(0xffffffffu, pa, 31);
            float Sr = __shfl_sync(0xffffffffu, pr, 31);
            float c1t = sm.rawC1[2 * lane][k] + sm.rawC1[2 * lane + 1][k];
            float c0t = sm.rawC0[2 * lane][k] + sm.rawC0[2 * lane + 1][k];
#pragma unroll
            for (int off = 16; off; off >>= 1) {
                c1t += __shfl_xor_sync(0xffffffffu, c1t, off);
                c0t += __shfl_xor_sync(0xffffffffu, c0t, off);
            }
            c0t += b2[(size_t)f * K_ + k];
            // prefix at m=2l+1: pa - a1 ; m=2l+2: pa ; m=0: 0
            float pA1 = pa - a1, pR1 = pr - r1;
            int m1 = 2 * lane + 1, m2 = 2 * lane + 2;
            sm.tab[m1][2 * k]     = c0t + Sr - 2.f * pR1;
            sm.tab[m1][2 * k + 1] = c1t + 2.f * pA1 - Sa;
            sm.tab[m2][2 * k]     = c0t + Sr - 2.f * pr;
            sm.tab[m2][2 * k + 1] = c1t + 2.f * pa - Sa;
            if (lane == 0) {
                sm.tab[0][2 * k]     = c0t + Sr;
                sm.tab[0][2 * k + 1] = c1t - Sa;
            }
        }
        __syncthreads();

        // main phase: 8 batch rows per thread
        float xv[8];
        int mm[8];
#pragma unroll
        for (int i = 0; i < 8; i++)
            xv[i] = g_sT[(size_t)f * B_ + i * 256 + tid];
#pragma unroll
        for (int i = 0; i < 8; i++) {
            int m = 0;
            float x = xv[i];
#pragma unroll
            for (int st = 64; st > 0; st >>= 1)
                if (sm.R[m + st - 1] <= x) m += st;
            mm[i] = m;
        }
#pragma unroll
        for (int i = 0; i < 8; i++) {
            const float4* tp = (const float4*)sm.tab[mm[i]];
            float4 t0 = tp[0], t1 = tp[1], t2 = tp[2], t3 = tp[3];
            const float x = xv[i];
            float s[8];
            s[0] = fmaf(t0.y, x, t0.x); s[1] = fmaf(t0.w, x, t0.z);
            s[2] = fmaf(t1.y, x, t1.x); s[3] = fmaf(t1.w, x, t1.z);
            s[4] = fmaf(t2.y, x, t2.x); s[5] = fmaf(t2.w, x, t2.z);
            s[6] = fmaf(t3.y, x, t3.x); s[7] = fmaf(t3.w, x, t3.z);
            float mx = -3.0e38f;
#pragma unroll
            for (int k = 0; k < K_; k++) {
                float pre = s[k];
                pre = fmaxf(pre, 0.01f * pre);   // second leaky
                pre *= sm.taus[k];               // tau
                s[k] = pre;
                mx = fmaxf(mx, pre);
            }
            float sum = 0.f;
#pragma unroll
            for (int k = 0; k < K_; k++) { s[k] = __expf(s[k] - mx); sum += s[k]; }
            const float inv = __frcp_rn(sum);
#pragma unroll
            for (int k = 0; k < K_; k++) s[k] *= inv;
            const size_t off = (size_t)(i * 256 + tid) * ZKP_ + ZPRE_ + f * K_;
            *(uint4*)(g_Zh + off) = pack8h(s);
        }
    } else if (blk < 1024) {
        // ---------------- B: M-build via fp16 split-2 MMA ----------------
        const int f = blk >> 1;
        ((float4*)smu.es)[tid] = ((const float4*)(emb + (size_t)f * K_ * D_))[tid];
        __syncthreads();

        const int lane = tid & 31;
        const int w = tid >> 5;
        const int g = lane >> 2;
        const int tg = lane & 3;
        const int o0 = w * 32;

        u32 bh[8][2], bl[8][2];
#pragma unroll
        for (int c = 0; c < 8; c++) {
            const float* er = &smu.es[g][c * 16];
            split2h(er[2 * tg],     er[2 * tg + 1], bh[c][0], bl[c][0]);
            split2h(er[2 * tg + 8], er[2 * tg + 9], bh[c][1], bl[c][1]);
        }

        float d0[4] = {0.f, 0.f, 0.f, 0.f};
        float d1[4] = {0.f, 0.f, 0.f, 0.f};

        const float* pwb = pw + ZPRE_ + (size_t)f * D_;
#pragma unroll
        for (int c = 0; c < 8; c++) {
            const int dc = c * 16;
#pragma unroll
            for (int mt = 0; mt < 2; mt++) {
                const float* r0 = pwb + (size_t)(o0 + mt * 16 + g) * PROJ_IN_ + dc + 2 * tg;
                const float* r1 = r0 + 8 * PROJ_IN_;
                float2 f0 = *(const float2*)(r0);
                float2 f1 = *(const float2*)(r1);
                float2 f2 = *(const float2*)(r0 + 8);
                float2 f3 = *(const float2*)(r1 + 8);
                u32 ah[4], al[4];
                split2h(f0.x, f0.y, ah[0], al[0]);
                split2h(f1.x, f1.y, ah[1], al[1]);
                split2h(f2.x, f2.y, ah[2], al[2]);
                split2h(f3.x, f3.y, ah[3], al[3]);
                float* dd = mt ? d1 : d0;
                mma_fp16(dd, ah, bh[c]);
                mma_fp16(dd, ah, bl[c]);
                mma_fp16(dd, al, bh[c]);
            }
        }

        const size_t cb = ZPRE_ + (size_t)f * K_ + 2 * tg;
#pragma unroll
        for (int mt = 0; mt < 2; mt++) {
            const float* dd = mt ? d1 : d0;
            const int ra = o0 + mt * 16 + g;
            __half2 h0 = __floats2half2_rn(dd[0], dd[1]);
            __half2 h1 = __floats2half2_rn(dd[2], dd[3]);
            *(u32*)(g_Bth + (size_t)ra * ZKP_ + cb)       = *(u32*)&h0;
            *(u32*)(g_Bth + (size_t)(ra + 8) * ZKP_ + cb) = *(u32*)&h1;
        }
    } else {
        // ---------------- B: copy proj_w cols 0..895 ----------------
        const int e = (blk - 1024) * 256 + tid;
        const int o = e / 112, j8 = e % 112;
        const int col = j8 * 8;
        const float4* p = (const float4*)(pw + (size_t)o * PROJ_IN_ + col);
        float4 v0 = p[0], v1 = p[1];
        float s[8] = {v0.x, v0.y, v0.z, v0.w, v1.x, v1.y, v1.z, v1.w};
        *(uint4*)(g_Bth + (size_t)o * ZKP_ + col) = pack8h(s);
    }
}

// ============================================================
// Kernel C: single-term fp16 mma.sync GEMM (C = Zh*Bh).
// BM=128 BN=128 BK=32, splitK=8 -> grid (16, 2, 8) = 256 CTAs.
// ============================================================
#define ROWB 80                        // 64B data + 16B pad (conflict-free ldsm)
#define MATB (128 * ROWB)              // 10240
#define STAGEB (2 * MATB)              // 20480: [A | B]
#define NSTAGE 4
#define SMEM_C_BYTES (NSTAGE * STAGEB) // 81920

__global__ __launch_bounds__(256, 2) void kernelC()
{
    extern __shared__ char smem[];
    const u32 smem_base = smem_u32(smem);
    const int tid = threadIdx.x;
    const int gm = blockIdx.x * 128;
    const int gn = blockIdx.y * 128;
    const int kbase = blockIdx.z * KSPLIT;

    const int lane = tid & 31;
    const int w = tid >> 5;
    const int g = lane >> 2;
    const int tg = lane & 3;
    const int m_off = (w & 3) * 32;
    const int n_off = (w >> 2) * 64;

    u32 aoff[2], boff[8];
#pragma unroll
    for (int i = 0; i < 2; i++)
        aoff[i] = (u32)((m_off + i * 16 + (lane & 15)) * ROWB + ((lane >> 4) << 4));
#pragma unroll
    for (int j = 0; j < 8; j++)
        boff[j] = (u32)((n_off + j * 8 + (lane & 7)) * ROWB + (((lane >> 3) & 1) << 4));

    float d[2][8][4];
#pragma unroll
    for (int i = 0; i < 2; i++)
#pragma unroll
        for (int j = 0; j < 8; j++)
#pragma unroll
            for (int c = 0; c < 4; c++) d[i][j][c] = 0.f;

#define FETCH(T, S)                                                                  \
    do {                                                                             \
        const int koff = kbase + (T) * BK;                                           \
        const u32 sb0 = smem_base + (S) * STAGEB;                                    \
        _Pragma("unroll")                                                            \
        for (int ci = 0; ci < 4; ci++) {                                             \
            int c = tid + ci * 256;                                                  \
            int idx = c & 511, row = idx >> 2, q = idx & 3;                          \
            const __half* src;                                                       \
            u32 dst;                                                                 \
            if (c < 512) {                                                           \
                src = g_Zh + (size_t)(gm + row) * ZKP_ + koff + q * 8;               \
                dst = sb0 + row * ROWB + q * 16;                                     \
            } else {                                                                 \
                src = g_Bth + (size_t)(gn + row) * ZKP_ + koff + q * 8;              \
                dst = sb0 + MATB + row * ROWB + q * 16;                              \
            }                                                                        \
            CP_ASYNC(dst, src);                                                      \
        }                                                                            \
    } while (0)

    FETCH(0, 0); CP_COMMIT();
    FETCH(1, 1); CP_COMMIT();
    FETCH(2, 2); CP_COMMIT();

#pragma unroll 1
    for (int t = 0; t < ITERS; t++) {
        CP_WAIT(2);
        __syncthreads();

        if (t + 3 < ITERS) FETCH(t + 3, (t + 3) & 3);
        CP_COMMIT();

        const u32 sb = smem_base + (t & 3) * STAGEB;

        u32 ah[2][2][4], bh[2][8][2];
#pragma unroll
        for (int s = 0; s < 2; s++) {
            const u32 kb = s * 32;
#pragma unroll
            for (int i = 0; i < 2; i++) ldsm_x4(ah[s][i], sb + aoff[i] + kb);
#pragma unroll
            for (int j = 0; j < 8; j++) ldsm_x2(bh[s][j], sb + MATB + boff[j] + kb);
        }
#pragma unroll
        for (int s = 0; s < 2; s++)
#pragma unroll
            for (int i = 0; i < 2; i++)
#pragma unroll
                for (int j = 0; j < 8; j++) mma_fp16(d[i][j], ah[s][i], bh[s][j]);
    }

    float* outp = g_CP + (size_t)blockIdx.z * (B_ * OUT_);
#pragma unroll
    for (int i = 0; i < 2; i++) {
        const int row = gm + m_off + 16 * i + g;
#pragma unroll
        for (int j = 0; j < 8; j++) {
            const int col = gn + n_off + 8 * j + 2 * tg;
            *(float2*)(outp + (size_t)row * OUT_ + col)       = make_float2(d[i][j][0], d[i][j][1]);
            *(float2*)(outp + (size_t)(row + 8) * OUT_ + col) = make_float2(d[i][j][2], d[i][j][3]);
        }
    }
#undef FETCH
}

// ============================================================
// Kernel D: out = relu(sum_z CP[z] + bias)
// ============================================================
__global__ __launch_bounds__(256) void kernelD(
    const float* __restrict__ pb, float* __restrict__ out)
{
    const int idx = blockIdx.x * 256 + threadIdx.x;
    float4 a = make_float4(0.f, 0.f, 0.f, 0.f);
#pragma unroll
    for (int z = 0; z < SPLITK; z++) {
        float4 v = ((const float4*)g_CP)[(size_t)z * (B_ * OUT_ / 4) + idx];
        a.x += v.x; a.y += v.y; a.z += v.z; a.w += v.w;
    }
    float4 bi = ((const float4*)pb)[idx & (OUT_ / 4 - 1)];
    float4 r;
    r.x = fmaxf(a.x + bi.x, 0.f);
    r.y = fmaxf(a.y + bi.y, 0.f);
    r.z = fmaxf(a.z + bi.z, 0.f);
    r.w = fmaxf(a.w + bi.w, 0.f);
    ((float4*)out)[idx] = r;
}

extern "C" void kernel_launch(void* const* d_in, const int* in_sizes, int n_in,
                              void* d_out, int out_size)
{
    const float* stat = (const float*)d_in[0];
    const float* asr  = (const float*)d_in[1];
    const float* mmv  = (const float*)d_in[2];
    const float* w1   = (const float*)d_in[3];
    const float* b1   = (const float*)d_in[4];
    const float* w2   = (const float*)d_in[5];
    const float* b2   = (const float*)d_in[6];
    const float* tau  = (const float*)d_in[7];
    const float* emb  = (const float*)d_in[8];
    const float* pw   = (const float*)d_in[9];
    const float* pb   = (const float*)d_in[10];
    float* out = (float*)d_out;

    static int smem_set = 0;
    if (!smem_set) {
        cudaFuncSetAttribute(kernelC, cudaFuncAttributeMaxDynamicSharedMemorySize, SMEM_C_BYTES);
        smem_set = 1;
    }

    kernelT<<<1024, 256>>>(stat);                                 // 1st
    kernelZ1<<<128, 256>>>(asr);                                  // 2nd
    kernelZ2<<<768, 256>>>(mmv);                                  // 3rd
    kernelAB<<<1024 + 112, 256>>>(w1, b1, w2, b2, tau, emb, pw);  // 4th <- profiled
    dim3 gc(B_ / 128, OUT_ / 128, SPLITK);
    kernelC<<<gc, 256, SMEM_C_BYTES>>>();                         // 5th
    kernelD<<<(B_ * OUT_ / 4) / 256, 256>>>(pb, out);             // 6th
}

// round 15
// speedup vs baseline: 1.2432x; 1.0546x over previous
#include <cuda_runtime.h>
#include <cuda_bf16.h>
#include <cuda_fp16.h>
#include <cstdint>

// Problem constants
#define B_    2048
#define F_    512
#define H_    64
#define K_    8
#define D_    128
#define ASR_  128
#define MM_   768
#define OUT_  256
#define ZPRE_ (ASR_ + MM_)          // 896
#define ZK_   (ZPRE_ + F_ * K_)     // 4992 (real contraction dim)
#define ZKP_  5120                  // padded (pad cols stay zero)
#define PROJ_IN_ (ASR_ + MM_ + F_ * D_)   // 66432
#define SPLITK 8
#define KSPLIT (ZKP_ / SPLITK)      // 640
#define BK    32
#define ITERS (KSPLIT / BK)         // 20

typedef unsigned long long ull;
typedef uint32_t u32;

__device__ __forceinline__ u32 smem_u32(const void* p) {
    u32 a;
    asm("{ .reg .u64 t; cvta.to.shared.u64 t, %1; cvt.u32.u64 %0, t; }" : "=r"(a) : "l"(p));
    return a;
}

// fp16 split: 2 floats -> hi half2 + lo half2
__device__ __forceinline__ void split2h(float x, float y, u32& h, u32& l) {
    __half2 hb = __floats2half2_rn(x, y);
    float2 back = __half22float2(hb);
    __half2 lb = __floats2half2_rn(x - back.x, y - back.y);
    h = *(u32*)&hb;
    l = *(u32*)&lb;
}

// 8 floats -> 8 fp16
__device__ __forceinline__ uint4 pack8h(const float* s) {
    __half2 h0 = __floats2half2_rn(s[0], s[1]);
    __half2 h1 = __floats2half2_rn(s[2], s[3]);
    __half2 h2 = __floats2half2_rn(s[4], s[5]);
    __half2 h3 = __floats2half2_rn(s[6], s[7]);
    return make_uint4(*(u32*)&h0, *(u32*)&h1, *(u32*)&h2, *(u32*)&h3);
}

// mma.sync m16n8k16 fp16 -> fp32
__device__ __forceinline__ void mma_fp16(float* d, const u32* a, const u32* b) {
    asm volatile(
        "mma.sync.aligned.m16n8k16.row.col.f32.f16.f16.f32 "
        "{%0,%1,%2,%3}, {%4,%5,%6,%7}, {%8,%9}, {%0,%1,%2,%3};"
        : "+f"(d[0]), "+f"(d[1]), "+f"(d[2]), "+f"(d[3])
        : "r"(a[0]), "r"(a[1]), "r"(a[2]), "r"(a[3]), "r"(b[0]), "r"(b[1]));
}

__device__ __forceinline__ void ldsm_x4(u32* r, u32 addr) {
    asm volatile("ldmatrix.sync.aligned.m8n8.x4.shared.b16 {%0,%1,%2,%3}, [%4];"
        : "=r"(r[0]), "=r"(r[1]), "=r"(r[2]), "=r"(r[3]) : "r"(addr));
}
__device__ __forceinline__ void ldsm_x2(u32* r, u32 addr) {
    asm volatile("ldmatrix.sync.aligned.m8n8.x2.shared.b16 {%0,%1}, [%2];"
        : "=r"(r[0]), "=r"(r[1]) : "r"(addr));
}

#define CP_ASYNC(dst, src) \
    asm volatile("cp.async.cg.shared.global [%0], [%1], 16;" :: "r"(dst), "l"(src) : "memory")
#define CP_COMMIT() asm volatile("cp.async.commit_group;" ::: "memory")
#define CP_WAIT(N)  asm volatile("cp.async.wait_group %0;" :: "n"(N) : "memory")

// ---------- device scratch (zero-initialized; pad cols never written) ----------
__device__ float g_sT[(size_t)F_ * B_];            // stat^T sanitized (4 MB)
__device__ __half g_Zh[(size_t)B_ * ZKP_];         // 21 MB (A operand, fp16)
__device__ __half g_Bth[(size_t)OUT_ * ZKP_];      // 2.6 MB (B operand, fp16)
__device__ float g_CP[(size_t)SPLITK * B_ * OUT_];

// ============================================================
// Kernel T: sanitize + transpose stat[2048][512] -> g_sT[512][2048]
// ============================================================
__global__ __launch_bounds__(256) void kernelT(const float* __restrict__ stat)
{
    __shared__ float tile[32][33];
    const int tid = threadIdx.x;
    const int tx = tid & 31, ty = tid >> 5;
    const int f0 = (blockIdx.x & 15) * 32, b0 = (blockIdx.x >> 4) * 32;
#pragma unroll
    for (int i = 0; i < 4; i++) {
        float v = stat[(size_t)(b0 + ty + i * 8) * F_ + f0 + tx];
        tile[ty + i * 8][tx] = (v >= 0.f) ? v : 0.f;   // NaN & neg -> 0
    }
    __syncthreads();
#pragma unroll
    for (int i = 0; i < 4; i++)
        g_sT[(size_t)(f0 + ty + i * 8) * B_ + b0 + tx] = tile[tx][ty + i * 8];
}

// ============================================================
// Kernel Z1: asr -> Zh cols 0..127 (fp16). 128 blocks.
// ============================================================
__global__ __launch_bounds__(256) void kernelZ1(const float* __restrict__ asr)
{
    const int e = blockIdx.x * 256 + threadIdx.x;   // 32768 = 2048 * 16
    const int b = e >> 4, j8 = e & 15;
    const int col = j8 * 8;
    const float4* p = (const float4*)(asr + (size_t)b * ASR_ + col);
    float4 v0 = p[0], v1 = p[1];
    float s[8] = {v0.x, v0.y, v0.z, v0.w, v1.x, v1.y, v1.z, v1.w};
    *(uint4*)(g_Zh + (size_t)b * ZKP_ + col) = pack8h(s);
}

// ============================================================
// Kernel Z2: mm -> Zh cols 128..895 (fp16). 768 blocks.
// ============================================================
__global__ __launch_bounds__(256) void kernelZ2(const float* __restrict__ mmv)
{
    const int e = blockIdx.x * 256 + threadIdx.x;   // 196608 = 2048 * 96
    const int b = e / 96, j8 = e % 96;
    const int col = j8 * 8;
    const float4* p = (const float4*)(mmv + (size_t)b * MM_ + col);
    float4 v0 = p[0], v1 = p[1];
    float s[8] = {v0.x, v0.y, v0.z, v0.w, v1.x, v1.y, v1.z, v1.w};
    *(uint4*)(g_Zh + (size_t)b * ZKP_ + ASR_ + col) = pack8h(s);
}

// ============================================================
// Kernel AB (fused, v4): PWL collapse with conflict-free SMEM:
//  - tab rows padded to 20 floats (80B) -> 8 bank classes, ~4x fewer
//    replays on the 4x LDS128 row gather
//  - R stored at strided index i+(i>>3) -> search positions spread
//    over all 32 banks (gcd(9,32)=1)
// ============================================================
#define RIDX(i) ((i) + ((i) >> 3))
#define TABW 20

struct SmemA {
    float rawA[64][8];     // a_jk
    float rawAR[64][8];    // a_jk * r_j
    float rawC1[64][8];
    float rawC0[64][8];
    float srtA[64][8];
    float srtAR[64][8];
    float R[144];          // strided sorted breakpoints (+INF pad)
    float tab[65][TABW];   // {A0,B0,...,A7,B7}, 80B row pitch
    float taus[8];
    float rtmp[64];
};
union SmemAB {
    SmemA a;
    float es[K_][D_];
};

__global__ __launch_bounds__(256) void kernelAB(
    const float* __restrict__ w1, const float* __restrict__ b1,
    const float* __restrict__ w2, const float* __restrict__ b2,
    const float* __restrict__ tau,
    const float* __restrict__ emb, const float* __restrict__ pw)
{
    __shared__ SmemAB smu;
    const int blk = blockIdx.x;
    const int tid = threadIdx.x;

    if (blk < 1024 && (blk & 1) == 0) {
        // ---------------- A: piecewise-linear MLP + softmax ----------------
        SmemA& sm = smu.a;
        const int f = blk >> 1;

        // phase 1: per-j coefficients
        if (tid < 64) {
            const int j = tid;
            const float* p = w1 + (size_t)f * 3 * H_;
            float w1s = p[j] + p[H_ + j] + p[2 * H_ + j];
            float b1v = b1[(size_t)f * H_ + j];
            float aw = fabsf(w1s);
            bool ok = aw > 1e-20f;
            float r = ok ? (-b1v / w1s) : 0.f;
            sm.rtmp[j] = r;
            const float* w2r = w2 + (size_t)f * H_ * K_ + j * K_;
#pragma unroll
            for (int k = 0; k < K_; k++) {
                float w2v = w2r[k];
                float a = ok ? (0.495f * aw * w2v) : 0.f;
                sm.rawA[j][k] = a;
                sm.rawAR[j][k] = a * r;
                sm.rawC1[j][k] = 0.505f * w1s * w2v;
                sm.rawC0[j][k] = 0.505f * b1v * w2v + (ok ? 0.f : 0.495f * fabsf(b1v) * w2v);
            }
        }
        if (tid >= 128 && tid < 136) sm.taus[tid - 128] = tau[(size_t)f * K_ + tid - 128];
        __syncthreads();

        // phase 2: rank + scatter to sorted (strided) order
        if (tid < 64) {
            const int j = tid;
            float r = sm.rtmp[j];
            int rank = 0;
#pragma unroll 8
            for (int i = 0; i < 64; i++) {
                float ri = sm.rtmp[i];
                rank += (ri < r) || (ri == r && i < j);
            }
            sm.R[RIDX(rank)] = r;
#pragma unroll
            for (int k = 0; k < K_; k++) {
                sm.srtA[rank][k]  = sm.rawA[j][k];
                sm.srtAR[rank][k] = sm.rawAR[j][k];
            }
        }
        if (tid >= 64 && tid < 128) sm.R[RIDX(tid)] = 3.0e38f;   // pad
        __syncthreads();

        // phase 3: warp w handles k=w; scan + table build
        const int w = tid >> 5, lane = tid & 31;
        if (w < 8) {
            const int k = w;
            float a0 = sm.srtA[2 * lane][k],  a1 = sm.srtA[2 * lane + 1][k];
            float r0 = sm.srtAR[2 * lane][k], r1 = sm.srtAR[2 * lane + 1][k];
            float pa = a0 + a1, pr = r0 + r1;
#pragma unroll
            for (int off = 1; off < 32; off <<= 1) {
                float ta = __shfl_up_sync(0xffffffffu, pa, off);
                float tr = __shfl_up_sync(0xffffffffu, pr, off);
                if (lane >= off) { pa += ta; pr += tr; }
            }
            float Sa = __shfl_sync(0xffffffffu, pa, 31);
            float Sr = __shfl_sync(0xffffffffu, pr, 31);
            float c1t = sm.rawC1[2 * lane][k] + sm.rawC1[2 * lane + 1][k];
            float c0t = sm.rawC0[2 * lane][k] + sm.rawC0[2 * lane + 1][k];
#pragma unroll
            for (int off = 16; off; off >>= 1) {
                c1t += __shfl_xor_sync(0xffffffffu, c1t, off);
                c0t += __shfl_xor_sync(0xffffffffu, c0t, off);
            }
            c0t += b2[(size_t)f * K_ + k];
            float pA1 = pa - a1, pR1 = pr - r1;
            int m1 = 2 * lane + 1, m2 = 2 * lane + 2;
            sm.tab[m1][2 * k]     = c0t + Sr - 2.f * pR1;
            sm.tab[m1][2 * k + 1] = c1t + 2.f * pA1 - Sa;
            sm.tab[m2][2 * k]     = c0t + Sr - 2.f * pr;
            sm.tab[m2][2 * k + 1] = c1t + 2.f * pa - Sa;
            if (lane == 0) {
                sm.tab[0][2 * k]     = c0t + Sr;
                sm.tab[0][2 * k + 1] = c1t - Sa;
            }
        }
        __syncthreads();

        // main phase: 8 batch rows per thread
        float xv[8];
        int mm[8];
#pragma unroll
        for (int i = 0; i < 8; i++)
            xv[i] = g_sT[(size_t)f * B_ + i * 256 + tid];
#pragma unroll
        for (int i = 0; i < 8; i++) {
            int m = 0;
            float x = xv[i];
#pragma unroll
            for (int st = 64; st > 0; st >>= 1)
                if (sm.R[RIDX(m + st - 1)] <= x) m += st;
            mm[i] = m;
        }
#pragma unroll
        for (int i = 0; i < 8; i++) {
            const float4* tp = (const float4*)&sm.tab[mm[i]][0];
            float4 t0 = tp[0], t1 = tp[1], t2 = tp[2], t3 = tp[3];
            const float x = xv[i];
            float s[8];
            s[0] = fmaf(t0.y, x, t0.x); s[1] = fmaf(t0.w, x, t0.z);
            s[2] = fmaf(t1.y, x, t1.x); s[3] = fmaf(t1.w, x, t1.z);
            s[4] = fmaf(t2.y, x, t2.x); s[5] = fmaf(t2.w, x, t2.z);
            s[6] = fmaf(t3.y, x, t3.x); s[7] = fmaf(t3.w, x, t3.z);
            float mx = -3.0e38f;
#pragma unroll
            for (int k = 0; k < K_; k++) {
                float pre = s[k];
                pre = fmaxf(pre, 0.01f * pre);   // second leaky
                pre *= sm.taus[k];               // tau
                s[k] = pre;
                mx = fmaxf(mx, pre);
            }
            float sum = 0.f;
#pragma unroll
            for (int k = 0; k < K_; k++) { s[k] = __expf(s[k] - mx); sum += s[k]; }
            const float inv = __frcp_rn(sum);
#pragma unroll
            for (int k = 0; k < K_; k++) s[k] *= inv;
            const size_t off = (size_t)(i * 256 + tid) * ZKP_ + ZPRE_ + f * K_;
            *(uint4*)(g_Zh + off) = pack8h(s);
        }
    } else if (blk < 1024) {
        // ---------------- B: M-build via fp16 split-2 MMA ----------------
        const int f = blk >> 1;
        ((float4*)smu.es)[tid] = ((const float4*)(emb + (size_t)f * K_ * D_))[tid];
        __syncthreads();

        const int lane = tid & 31;
        const int w = tid >> 5;
        const int g = lane >> 2;
        const int tg = lane & 3;
        const int o0 = w * 32;

        u32 bh[8][2], bl[8][2];
#pragma unroll
        for (int c = 0; c < 8; c++) {
            const float* er = &smu.es[g][c * 16];
            split2h(er[2 * tg],     er[2 * tg + 1], bh[c][0], bl[c][0]);
            split2h(er[2 * tg + 8], er[2 * tg + 9], bh[c][1], bl[c][1]);
        }

        float d0[4] = {0.f, 0.f, 0.f, 0.f};
        float d1[4] = {0.f, 0.f, 0.f, 0.f};

        const float* pwb = pw + ZPRE_ + (size_t)f * D_;
#pragma unroll
        for (int c = 0; c < 8; c++) {
            const int dc = c * 16;
#pragma unroll
            for (int mt = 0; mt < 2; mt++) {
                const float* r0 = pwb + (size_t)(o0 + mt * 16 + g) * PROJ_IN_ + dc + 2 * tg;
                const float* r1 = r0 + 8 * PROJ_IN_;
                float2 f0 = *(const float2*)(r0);
                float2 f1 = *(const float2*)(r1);
                float2 f2 = *(const float2*)(r0 + 8);
                float2 f3 = *(const float2*)(r1 + 8);
                u32 ah[4], al[4];
                split2h(f0.x, f0.y, ah[0], al[0]);
                split2h(f1.x, f1.y, ah[1], al[1]);
                split2h(f2.x, f2.y, ah[2], al[2]);
                split2h(f3.x, f3.y, ah[3], al[3]);
                float* dd = mt ? d1 : d0;
                mma_fp16(dd, ah, bh[c]);
                mma_fp16(dd, ah, bl[c]);
                mma_fp16(dd, al, bh[c]);
            }
        }

        const size_t cb = ZPRE_ + (size_t)f * K_ + 2 * tg;
#pragma unroll
        for (int mt = 0; mt < 2; mt++) {
            const float* dd = mt ? d1 : d0;
            const int ra = o0 + mt * 16 + g;
            __half2 h0 = __floats2half2_rn(dd[0], dd[1]);
            __half2 h1 = __floats2half2_rn(dd[2], dd[3]);
            *(u32*)(g_Bth + (size_t)ra * ZKP_ + cb)       = *(u32*)&h0;
            *(u32*)(g_Bth + (size_t)(ra + 8) * ZKP_ + cb) = *(u32*)&h1;
        }
    } else {
        // ---------------- B: copy proj_w cols 0..895 ----------------
        const int e = (blk - 1024) * 256 + tid;
        const int o = e / 112, j8 = e % 112;
        const int col = j8 * 8;
        const float4* p = (const float4*)(pw + (size_t)o * PROJ_IN_ + col);
        float4 v0 = p[0], v1 = p[1];
        float s[8] = {v0.x, v0.y, v0.z, v0.w, v1.x, v1.y, v1.z, v1.w};
        *(uint4*)(g_Bth + (size_t)o * ZKP_ + col) = pack8h(s);
    }
}

// ============================================================
// Kernel C: single-term fp16 mma.sync GEMM (C = Zh*Bh).
// BM=128 BN=128 BK=32, splitK=8 -> grid (16, 2, 8) = 256 CTAs.
// ============================================================
#define ROWB 80                        // 64B data + 16B pad (conflict-free ldsm)
#define MATB (128 * ROWB)              // 10240
#define STAGEB (2 * MATB)              // 20480: [A | B]
#define NSTAGE 4
#define SMEM_C_BYTES (NSTAGE * STAGEB) // 81920

__global__ __launch_bounds__(256, 2) void kernelC()
{
    extern __shared__ char smem[];
    const u32 smem_base = smem_u32(smem);
    const int tid = threadIdx.x;
    const int gm = blockIdx.x * 128;
    const int gn = blockIdx.y * 128;
    const int kbase = blockIdx.z * KSPLIT;

    const int lane = tid & 31;
    const int w = tid >> 5;
    const int g = lane >> 2;
    const int tg = lane & 3;
    const int m_off = (w & 3) * 32;
    const int n_off = (w >> 2) * 64;

    u32 aoff[2], boff[8];
#pragma unroll
    for (int i = 0; i < 2; i++)
        aoff[i] = (u32)((m_off + i * 16 + (lane & 15)) * ROWB + ((lane >> 4) << 4));
#pragma unroll
    for (int j = 0; j < 8; j++)
        boff[j] = (u32)((n_off + j * 8 + (lane & 7)) * ROWB + (((lane >> 3) & 1) << 4));

    float d[2][8][4];
#pragma unroll
    for (int i = 0; i < 2; i++)
#pragma unroll
        for (int j = 0; j < 8; j++)
#pragma unroll
            for (int c = 0; c < 4; c++) d[i][j][c] = 0.f;

#define FETCH(T, S)                                                                  \
    do {                                                                             \
        const int koff = kbase + (T) * BK;                                           \
        const u32 sb0 = smem_base + (S) * STAGEB;                                    \
        _Pragma("unroll")                                                            \
        for (int ci = 0; ci < 4; ci++) {                                             \
            int c = tid + ci * 256;                                                  \
            int idx = c & 511, row = idx >> 2, q = idx & 3;                          \
            const __half* src;                                                       \
            u32 dst;                                                                 \
            if (c < 512) {                                                           \
                src = g_Zh + (size_t)(gm + row) * ZKP_ + koff + q * 8;               \
                dst = sb0 + row * ROWB + q * 16;                                     \
            } else {                                                                 \
                src = g_Bth + (size_t)(gn + row) * ZKP_ + koff + q * 8;              \
                dst = sb0 + MATB + row * ROWB + q * 16;                              \
            }                                                                        \
            CP_ASYNC(dst, src);                                                      \
        }                                                                            \
    } while (0)

    FETCH(0, 0); CP_COMMIT();
    FETCH(1, 1); CP_COMMIT();
    FETCH(2, 2); CP_COMMIT();

#pragma unroll 1
    for (int t = 0; t < ITERS; t++) {
        CP_WAIT(2);
        __syncthreads();

        if (t + 3 < ITERS) FETCH(t + 3, (t + 3) & 3);
        CP_COMMIT();

        const u32 sb = smem_base + (t & 3) * STAGEB;

        u32 ah[2][2][4], bh[2][8][2];
#pragma unroll
        for (int s = 0; s < 2; s++) {
            const u32 kb = s * 32;
#pragma unroll
            for (int i = 0; i < 2; i++) ldsm_x4(ah[s][i], sb + aoff[i] + kb);
#pragma unroll
            for (int j = 0; j < 8; j++) ldsm_x2(bh[s][j], sb + MATB + boff[j] + kb);
        }
#pragma unroll
        for (int s = 0; s < 2; s++)
#pragma unroll
            for (int i = 0; i < 2; i++)
#pragma unroll
                for (int j = 0; j < 8; j++) mma_fp16(d[i][j], ah[s][i], bh[s][j]);
    }

    float* outp = g_CP + (size_t)blockIdx.z * (B_ * OUT_);
#pragma unroll
    for (int i = 0; i < 2; i++) {
        const int row = gm + m_off + 16 * i + g;
#pragma unroll
        for (int j = 0; j < 8; j++) {
            const int col = gn + n_off + 8 * j + 2 * tg;
            *(float2*)(outp + (size_t)row * OUT_ + col)       = make_float2(d[i][j][0], d[i][j][1]);
            *(float2*)(outp + (size_t)(row + 8) * OUT_ + col) = make_float2(d[i][j][2], d[i][j][3]);
        }
    }
#undef FETCH
}

// ============================================================
// Kernel D: out = relu(sum_z CP[z] + bias)
// ============================================================
__global__ __launch_bounds__(256) void kernelD(
    const float* __restrict__ pb, float* __restrict__ out)
{
    const int idx = blockIdx.x * 256 + threadIdx.x;
    float4 a = make_float4(0.f, 0.f, 0.f, 0.f);
#pragma unroll
    for (int z = 0; z < SPLITK; z++) {
        float4 v = ((const float4*)g_CP)[(size_t)z * (B_ * OUT_ / 4) + idx];
        a.x += v.x; a.y += v.y; a.z += v.z; a.w += v.w;
    }
    float4 bi = ((const float4*)pb)[idx & (OUT_ / 4 - 1)];
    float4 r;
    r.x = fmaxf(a.x + bi.x, 0.f);
    r.y = fmaxf(a.y + bi.y, 0.f);
    r.z = fmaxf(a.z + bi.z, 0.f);
    r.w = fmaxf(a.w + bi.w, 0.f);
    ((float4*)out)[idx] = r;
}

extern "C" void kernel_launch(void* const* d_in, const int* in_sizes, int n_in,
                              void* d_out, int out_size)
{
    const float* stat = (const float*)d_in[0];
    const float* asr  = (const float*)d_in[1];
    const float* mmv  = (const float*)d_in[2];
    const float* w1   = (const float*)d_in[3];
    const float* b1   = (const float*)d_in[4];
    const float* w2   = (const float*)d_in[5];
    const float* b2   = (const float*)d_in[6];
    const float* tau  = (const float*)d_in[7];
    const float* emb  = (const float*)d_in[8];
    const float* pw   = (const float*)d_in[9];
    const float* pb   = (const float*)d_in[10];
    float* out = (float*)d_out;

    static int smem_set = 0;
    if (!smem_set) {
        cudaFuncSetAttribute(kernelC, cudaFuncAttributeMaxDynamicSharedMemorySize, SMEM_C_BYTES);
        smem_set = 1;
    }

    kernelT<<<1024, 256>>>(stat);                                 // 1st
    kernelZ1<<<128, 256>>>(asr);                                  // 2nd
    kernelZ2<<<768, 256>>>(mmv);                                  // 3rd
    kernelAB<<<1024 + 112, 256>>>(w1, b1, w2, b2, tau, emb, pw);  // 4th <- profiled
    dim3 gc(B_ / 128, OUT_ / 128, SPLITK);
    kernelC<<<gc, 256, SMEM_C_BYTES>>>();                         // 5th
    kernelD<<<(B_ * OUT_ / 4) / 256, 256>>>(pb, out);             // 6th
}

// round 16
// speedup vs baseline: 1.3567x; 1.0913x over previous
#include <cuda_runtime.h>
#include <cuda_bf16.h>
#include <cuda_fp16.h>
#include <cstdint>

// Problem constants
#define B_    2048
#define F_    512
#define H_    64
#define K_    8
#define D_    128
#define ASR_  128
#define MM_   768
#define OUT_  256
#define ZPRE_ (ASR_ + MM_)          // 896
#define ZK_   (ZPRE_ + F_ * K_)     // 4992 (real contraction dim)
#define ZKP_  5120                  // padded (pad rows stay zero)
#define PROJ_IN_ (ASR_ + MM_ + F_ * D_)   // 66432
#define SPLITK 8
#define KSPLIT (ZKP_ / SPLITK)      // 640
#define BK    32
#define ITERS (KSPLIT / BK)         // 20

typedef unsigned long long ull;
typedef uint32_t u32;

__device__ __forceinline__ u32 smem_u32(const void* p) {
    u32 a;
    asm("{ .reg .u64 t; cvta.to.shared.u64 t, %1; cvt.u32.u64 %0, t; }" : "=r"(a) : "l"(p));
    return a;
}

// fp16 split: 2 floats -> hi half2 + lo half2
__device__ __forceinline__ void split2h(float x, float y, u32& h, u32& l) {
    __half2 hb = __floats2half2_rn(x, y);
    float2 back = __half22float2(hb);
    __half2 lb = __floats2half2_rn(x - back.x, y - back.y);
    h = *(u32*)&hb;
    l = *(u32*)&lb;
}

// 8 floats -> 8 fp16
__device__ __forceinline__ uint4 pack8h(const float* s) {
    __half2 h0 = __floats2half2_rn(s[0], s[1]);
    __half2 h1 = __floats2half2_rn(s[2], s[3]);
    __half2 h2 = __floats2half2_rn(s[4], s[5]);
    __half2 h3 = __floats2half2_rn(s[6], s[7]);
    return make_uint4(*(u32*)&h0, *(u32*)&h1, *(u32*)&h2, *(u32*)&h3);
}

// mma.sync m16n8k16 fp16 -> fp32
__device__ __forceinline__ void mma_fp16(float* d, const u32* a, const u32* b) {
    asm volatile(
        "mma.sync.aligned.m16n8k16.row.col.f32.f16.f16.f32 "
        "{%0,%1,%2,%3}, {%4,%5,%6,%7}, {%8,%9}, {%0,%1,%2,%3};"
        : "+f"(d[0]), "+f"(d[1]), "+f"(d[2]), "+f"(d[3])
        : "r"(a[0]), "r"(a[1]), "r"(a[2]), "r"(a[3]), "r"(b[0]), "r"(b[1]));
}

__device__ __forceinline__ void ldsm_x4_t(u32* r, u32 addr) {
    asm volatile("ldmatrix.sync.aligned.m8n8.x4.trans.shared.b16 {%0,%1,%2,%3}, [%4];"
        : "=r"(r[0]), "=r"(r[1]), "=r"(r[2]), "=r"(r[3]) : "r"(addr));
}
__device__ __forceinline__ void ldsm_x2(u32* r, u32 addr) {
    asm volatile("ldmatrix.sync.aligned.m8n8.x2.shared.b16 {%0,%1}, [%2];"
        : "=r"(r[0]), "=r"(r[1]) : "r"(addr));
}

#define CP_ASYNC(dst, src) \
    asm volatile("cp.async.cg.shared.global [%0], [%1], 16;" :: "r"(dst), "l"(src) : "memory")
#define CP_COMMIT() asm volatile("cp.async.commit_group;" ::: "memory")
#define CP_WAIT(N)  asm volatile("cp.async.wait_group %0;" :: "n"(N) : "memory")

// ---------- device scratch (zero-initialized; pad rows never written) ----------
__device__ float g_sT[(size_t)F_ * B_];            // stat^T sanitized (4 MB)
__device__ __half g_Zt[(size_t)ZKP_ * B_];         // 20 MB  A operand, K-MAJOR [k][b]
__device__ __half g_Bth[(size_t)OUT_ * ZKP_];      // 2.6 MB B operand [n][k]
__device__ float g_CP[(size_t)SPLITK * B_ * OUT_];

// ============================================================
// Kernel TZ (fused transposes):
//  blk <1024        : sanitize+transpose stat -> g_sT
//  1024..1279       : transpose asr  -> Zt rows 0..127
//  1280..2815       : transpose mm   -> Zt rows 128..895
// ============================================================
__global__ __launch_bounds__(256) void kernelTZ(
    const float* __restrict__ stat,
    const float* __restrict__ asr, const float* __restrict__ mmv)
{
    __shared__ float tile[32][33];
    const int blk = blockIdx.x;
    const int tid = threadIdx.x;
    const int tx = tid & 31, ty = tid >> 5;

    if (blk < 1024) {
        const int f0 = (blk & 15) * 32, b0 = (blk >> 4) * 32;
#pragma unroll
        for (int i = 0; i < 4; i++) {
            float v = stat[(size_t)(b0 + ty + i * 8) * F_ + f0 + tx];
            tile[ty + i * 8][tx] = (v >= 0.f) ? v : 0.f;   // NaN & neg -> 0
        }
        __syncthreads();
#pragma unroll
        for (int i = 0; i < 4; i++)
            g_sT[(size_t)(f0 + ty + i * 8) * B_ + b0 + tx] = tile[tx][ty + i * 8];
    } else if (blk < 1024 + 256) {
        const int idx = blk - 1024;
        const int k0 = (idx & 3) * 32, b0 = (idx >> 2) * 32;
#pragma unroll
        for (int i = 0; i < 4; i++)
            tile[ty + i * 8][tx] = asr[(size_t)(b0 + ty + i * 8) * ASR_ + k0 + tx];
        __syncthreads();
#pragma unroll
        for (int i = 0; i < 4; i++)
            g_Zt[(size_t)(k0 + ty + i * 8) * B_ + b0 + tx] =
                __float2half_rn(tile[tx][ty + i * 8]);
    } else {
        const int idx = blk - 1280;
        const int k0 = (idx % 24) * 32, b0 = (idx / 24) * 32;
#pragma unroll
        for (int i = 0; i < 4; i++)
            tile[ty + i * 8][tx] = mmv[(size_t)(b0 + ty + i * 8) * MM_ + k0 + tx];
        __syncthreads();
#pragma unroll
        for (int i = 0; i < 4; i++)
            g_Zt[(size_t)(ASR_ + k0 + ty + i * 8) * B_ + b0 + tx] =
                __float2half_rn(tile[tx][ty + i * 8]);
    }
}

// ============================================================
// Kernel AB (fused): PWL MLP (A) + M-build (B), k-major output.
//   blk < 1024: even -> A (f = blk>>1), odd -> B M-build (f = blk>>1)
//   blk >= 1024: B copy of proj_w cols 0..895 (112 blocks)
// A stores are staged in SMEM and written COALESCED to Zt rows.
// ============================================================
#define RIDX(i) ((i) + ((i) >> 3))
#define TABW 20

struct SmemA {
    float rawA[64][8];
    float rawAR[64][8];
    float rawC1[64][8];
    float rawC0[64][8];
    float srtA[64][8];
    float srtAR[64][8];
    float R[144];          // strided sorted breakpoints (+INF pad)
    float tab[65][TABW];   // {A0,B0,...,A7,B7}, 80B row pitch
    float taus[8];
    float rtmp[64];
    __half stg[8][264];    // k-major staging: 8 k-rows x 256 b (+pad)
};
union SmemAB {
    SmemA a;
    float es[K_][D_];
};

__global__ __launch_bounds__(256) void kernelAB(
    const float* __restrict__ w1, const float* __restrict__ b1,
    const float* __restrict__ w2, const float* __restrict__ b2,
    const float* __restrict__ tau,
    const float* __restrict__ emb, const float* __restrict__ pw)
{
    __shared__ SmemAB smu;
    const int blk = blockIdx.x;
    const int tid = threadIdx.x;

    if (blk < 1024 && (blk & 1) == 0) {
        // ---------------- A: piecewise-linear MLP + softmax ----------------
        SmemA& sm = smu.a;
        const int f = blk >> 1;

        if (tid < 64) {
            const int j = tid;
            const float* p = w1 + (size_t)f * 3 * H_;
            float w1s = p[j] + p[H_ + j] + p[2 * H_ + j];
            float b1v = b1[(size_t)f * H_ + j];
            float aw = fabsf(w1s);
            bool ok = aw > 1e-20f;
            float r = ok ? (-b1v / w1s) : 0.f;
            sm.rtmp[j] = r;
            const float* w2r = w2 + (size_t)f * H_ * K_ + j * K_;
#pragma unroll
            for (int k = 0; k < K_; k++) {
                float w2v = w2r[k];
                float a = ok ? (0.495f * aw * w2v) : 0.f;
                sm.rawA[j][k] = a;
                sm.rawAR[j][k] = a * r;
                sm.rawC1[j][k] = 0.505f * w1s * w2v;
                sm.rawC0[j][k] = 0.505f * b1v * w2v + (ok ? 0.f : 0.495f * fabsf(b1v) * w2v);
            }
        }
        if (tid >= 128 && tid < 136) sm.taus[tid - 128] = tau[(size_t)f * K_ + tid - 128];
        __syncthreads();

        if (tid < 64) {
            const int j = tid;
            float r = sm.rtmp[j];
            int rank = 0;
#pragma unroll 8
            for (int i = 0; i < 64; i++) {
                float ri = sm.rtmp[i];
                rank += (ri < r) || (ri == r && i < j);
            }
            sm.R[RIDX(rank)] = r;
#pragma unroll
            for (int k = 0; k < K_; k++) {
                sm.srtA[rank][k]  = sm.rawA[j][k];
                sm.srtAR[rank][k] = sm.rawAR[j][k];
            }
        }
        if (tid >= 64 && tid < 128) sm.R[RIDX(tid)] = 3.0e38f;   // pad
        __syncthreads();

        const int w = tid >> 5, lane = tid & 31;
        if (w < 8) {
            const int k = w;
            float a0 = sm.srtA[2 * lane][k],  a1 = sm.srtA[2 * lane + 1][k];
            float r0 = sm.srtAR[2 * lane][k], r1 = sm.srtAR[2 * lane + 1][k];
            float pa = a0 + a1, pr = r0 + r1;
#pragma unroll
            for (int off = 1; off < 32; off <<= 1) {
                float ta = __shfl_up_sync(0xffffffffu, pa, off);
                float tr = __shfl_up_sync(0xffffffffu, pr, off);
                if (lane >= off) { pa += ta; pr += tr; }
            }
            float Sa = __shfl_sync(0xffffffffu, pa, 31);
            float Sr = __shfl_sync(0xffffffffu, pr, 31);
            float c1t = sm.rawC1[2 * lane][k] + sm.rawC1[2 * lane + 1][k];
            float c0t = sm.rawC0[2 * lane][k] + sm.rawC0[2 * lane + 1][k];
#pragma unroll
            for (int off = 16; off; off >>= 1) {
                c1t += __shfl_xor_sync(0xffffffffu, c1t, off);
                c0t += __shfl_xor_sync(0xffffffffu, c0t, off);
            }
            c0t += b2[(size_t)f * K_ + k];
            float pA1 = pa - a1, pR1 = pr - r1;
            int m1 = 2 * lane + 1, m2 = 2 * lane + 2;
            sm.tab[m1][2 * k]     = c0t + Sr - 2.f * pR1;
            sm.tab[m1][2 * k + 1] = c1t + 2.f * pA1 - Sa;
            sm.tab[m2][2 * k]     = c0t + Sr - 2.f * pr;
            sm.tab[m2][2 * k + 1] = c1t + 2.f * pa - Sa;
            if (lane == 0) {
                sm.tab[0][2 * k]     = c0t + Sr;
                sm.tab[0][2 * k + 1] = c1t - Sa;
            }
        }
        __syncthreads();

        // main phase: 8 batch rows per thread, staged k-major output
        float xv[8];
        int mm[8];
#pragma unroll
        for (int i = 0; i < 8; i++)
            xv[i] = g_sT[(size_t)f * B_ + i * 256 + tid];
#pragma unroll
        for (int i = 0; i < 8; i++) {
            int m = 0;
            float x = xv[i];
#pragma unroll
            for (int st = 64; st > 0; st >>= 1)
                if (sm.R[RIDX(m + st - 1)] <= x) m += st;
            mm[i] = m;
        }
        const int orow = tid >> 5, och = tid & 31;     // for coalesced write-out
        __half* zrow_base = g_Zt + (size_t)(ZPRE_ + f * K_ + orow) * B_ + och * 8;
#pragma unroll 1
        for (int i = 0; i < 8; i++) {
            const float4* tp = (const float4*)&sm.tab[mm[i]][0];
            float4 t0 = tp[0], t1 = tp[1], t2 = tp[2], t3 = tp[3];
            const float x = xv[i];
            float s[8];
            s[0] = fmaf(t0.y, x, t0.x); s[1] = fmaf(t0.w, x, t0.z);
            s[2] = fmaf(t1.y, x, t1.x); s[3] = fmaf(t1.w, x, t1.z);
            s[4] = fmaf(t2.y, x, t2.x); s[5] = fmaf(t2.w, x, t2.z);
            s[6] = fmaf(t3.y, x, t3.x); s[7] = fmaf(t3.w, x, t3.z);
            float mx = -3.0e38f;
#pragma unroll
            for (int k = 0; k < K_; k++) {
                float pre = s[k];
                pre = fmaxf(pre, 0.01f * pre);   // second leaky
                pre *= sm.taus[k];               // tau
                s[k] = pre;
                mx = fmaxf(mx, pre);
            }
            float sum = 0.f;
#pragma unroll
            for (int k = 0; k < K_; k++) { s[k] = __expf(s[k] - mx); sum += s[k]; }
            const float inv = __frcp_rn(sum);
#pragma unroll
            for (int k = 0; k < K_; k++)
                sm.stg[k][tid] = __float2half_rn(s[k] * inv);
            __syncthreads();
            uint4 v = *(const uint4*)&sm.stg[orow][och * 8];
            *(uint4*)(zrow_base + i * 256) = v;     // coalesced 512B/warp
            __syncthreads();
        }
    } else if (blk < 1024) {
        // ---------------- B: M-build via fp16 split-2 MMA ----------------
        const int f = blk >> 1;
        ((float4*)smu.es)[tid] = ((const float4*)(emb + (size_t)f * K_ * D_))[tid];
        __syncthreads();

        const int lane = tid & 31;
        const int w = tid >> 5;
        const int g = lane >> 2;
        const int tg = lane & 3;
        const int o0 = w * 32;

        u32 bh[8][2], bl[8][2];
#pragma unroll
        for (int c = 0; c < 8; c++) {
            const float* er = &smu.es[g][c * 16];
            split2h(er[2 * tg],     er[2 * tg + 1], bh[c][0], bl[c][0]);
            split2h(er[2 * tg + 8], er[2 * tg + 9], bh[c][1], bl[c][1]);
        }

        float d0[4] = {0.f, 0.f, 0.f, 0.f};
        float d1[4] = {0.f, 0.f, 0.f, 0.f};

        const float* pwb = pw + ZPRE_ + (size_t)f * D_;
#pragma unroll
        for (int c = 0; c < 8; c++) {
            const int dc = c * 16;
#pragma unroll
            for (int mt = 0; mt < 2; mt++) {
                const float* r0 = pwb + (size_t)(o0 + mt * 16 + g) * PROJ_IN_ + dc + 2 * tg;
                const float* r1 = r0 + 8 * PROJ_IN_;
                float2 f0 = *(const float2*)(r0);
                float2 f1 = *(const float2*)(r1);
                float2 f2 = *(const float2*)(r0 + 8);
                float2 f3 = *(const float2*)(r1 + 8);
                u32 ah[4], al[4];
                split2h(f0.x, f0.y, ah[0], al[0]);
                split2h(f1.x, f1.y, ah[1], al[1]);
                split2h(f2.x, f2.y, ah[2], al[2]);
                split2h(f3.x, f3.y, ah[3], al[3]);
                float* dd = mt ? d1 : d0;
                mma_fp16(dd, ah, bh[c]);
                mma_fp16(dd, ah, bl[c]);
                mma_fp16(dd, al, bh[c]);
            }
        }

        const size_t cb = ZPRE_ + (size_t)f * K_ + 2 * tg;
#pragma unroll
        for (int mt = 0; mt < 2; mt++) {
            const float* dd = mt ? d1 : d0;
            const int ra = o0 + mt * 16 + g;
            __half2 h0 = __floats2half2_rn(dd[0], dd[1]);
            __half2 h1 = __floats2half2_rn(dd[2], dd[3]);
            *(u32*)(g_Bth + (size_t)ra * ZKP_ + cb)       = *(u32*)&h0;
            *(u32*)(g_Bth + (size_t)(ra + 8) * ZKP_ + cb) = *(u32*)&h1;
        }
    } else {
        // ---------------- B: copy proj_w cols 0..895 ----------------
        const int e = (blk - 1024) * 256 + tid;
        const int o = e / 112, j8 = e % 112;
        const int col = j8 * 8;
        const float4* p = (const float4*)(pw + (size_t)o * PROJ_IN_ + col);
        float4 v0 = p[0], v1 = p[1];
        float s[8] = {v0.x, v0.y, v0.z, v0.w, v1.x, v1.y, v1.z, v1.w};
        *(uint4*)(g_Bth + (size_t)o * ZKP_ + col) = pack8h(s);
    }
}

// ============================================================
// Kernel C: single-term fp16 mma.sync GEMM (C = Z*B).
// A operand now K-MAJOR: SMEM tile [32 k][128 b] pitch 272B,
// fragments via ldmatrix.x4.trans. B path unchanged.
// BM=128 BN=128 BK=32, splitK=8 -> grid (16, 2, 8) = 256 CTAs.
// ============================================================
#define AROWB 272                       // 256B data + 16B pad
#define A_MATB (32 * AROWB)             // 8704
#define ROWB 80
#define MATB (128 * ROWB)               // 10240
#define STAGEB (A_MATB + MATB)          // 18944: [A | B]
#define NSTAGE 4
#define SMEM_C_BYTES (NSTAGE * STAGEB)  // 75776

__global__ __launch_bounds__(256, 2) void kernelC()
{
    extern __shared__ char smem[];
    const u32 smem_base = smem_u32(smem);
    const int tid = threadIdx.x;
    const int gm = blockIdx.x * 128;
    const int gn = blockIdx.y * 128;
    const int kbase = blockIdx.z * KSPLIT;

    const int lane = tid & 31;
    const int w = tid >> 5;
    const int g = lane >> 2;
    const int tg = lane & 3;
    const int m_off = (w & 3) * 32;
    const int n_off = (w >> 2) * 64;

    // trans-A per-lane base: tile t = lane>>3, row r = lane&7
    // t0:(m+0,k+0) t1:(m+8,k+0) t2:(m+0,k+8) t3:(m+8,k+8)
    const int t_ = lane >> 3, r_ = lane & 7;
    const u32 abase = (u32)(((t_ >= 2 ? 8 : 0) + r_) * AROWB + (t_ & 1) * 16);
    u32 aoff[2], boff[8];
#pragma unroll
    for (int i = 0; i < 2; i++)
        aoff[i] = abase + (u32)((m_off + i * 16) * 2);
#pragma unroll
    for (int j = 0; j < 8; j++)
        boff[j] = (u32)(A_MATB + (n_off + j * 8 + (lane & 7)) * ROWB + (((lane >> 3) & 1) << 4));

    float d[2][8][4];
#pragma unroll
    for (int i = 0; i < 2; i++)
#pragma unroll
        for (int j = 0; j < 8; j++)
#pragma unroll
            for (int c = 0; c < 4; c++) d[i][j][c] = 0.f;

    // cp.async: 1024 chunks. c<512: A (k-major): krow=idx>>4, bq=idx&15.
    //           c>=512: B rows: row=idx>>2, q=idx&3.
#define FETCH(T, S)                                                                  \
    do {                                                                             \
        const int koff = kbase + (T) * BK;                                           \
        const u32 sb0 = smem_base + (S) * STAGEB;                                    \
        _Pragma("unroll")                                                            \
        for (int ci = 0; ci < 4; ci++) {                                             \
            int c = tid + ci * 256;                                                  \
            const __half* src;                                                       \
            u32 dst;                                                                 \
            if (c < 512) {                                                           \
                int krow = c >> 4, bq = c & 15;                                      \
                src = g_Zt + (size_t)(koff + krow) * B_ + gm + bq * 8;               \
                dst = sb0 + krow * AROWB + bq * 16;                                  \
            } else {                                                                 \
                int idx = c & 511, row = idx >> 2, q = idx & 3;                      \
                src = g_Bth + (size_t)(gn + row) * ZKP_ + koff + q * 8;              \
                dst = sb0 + A_MATB + row * ROWB + q * 16;                            \
            }                                                                        \
            CP_ASYNC(dst, src);                                                      \
        }                                                                            \
    } while (0)

    FETCH(0, 0); CP_COMMIT();
    FETCH(1, 1); CP_COMMIT();
    FETCH(2, 2); CP_COMMIT();

#pragma unroll 1
    for (int t = 0; t < ITERS; t++) {
        CP_WAIT(2);
        __syncthreads();

        if (t + 3 < ITERS) FETCH(t + 3, (t + 3) & 3);
        CP_COMMIT();

        const u32 sb = smem_base + (t & 3) * STAGEB;

        u32 ah[2][2][4], bh[2][8][2];
#pragma unroll
        for (int s = 0; s < 2; s++) {
#pragma unroll
            for (int i = 0; i < 2; i++)
                ldsm_x4_t(ah[s][i], sb + aoff[i] + s * (16 * AROWB));
#pragma unroll
            for (int j = 0; j < 8; j++)
                ldsm_x2(bh[s][j], sb + boff[j] + s * 32);
        }
#pragma unroll
        for (int s = 0; s < 2; s++)
#pragma unroll
            for (int i = 0; i < 2; i++)
#pragma unroll
                for (int j = 0; j < 8; j++) mma_fp16(d[i][j], ah[s][i], bh[s][j]);
    }

    float* outp = g_CP + (size_t)blockIdx.z * (B_ * OUT_);
#pragma unroll
    for (int i = 0; i < 2; i++) {
        const int row = gm + m_off + 16 * i + g;
#pragma unroll
        for (int j = 0; j < 8; j++) {
            const int col = gn + n_off + 8 * j + 2 * tg;
            *(float2*)(outp + (size_t)row * OUT_ + col)       = make_float2(d[i][j][0], d[i][j][1]);
            *(float2*)(outp + (size_t)(row + 8) * OUT_ + col) = make_float2(d[i][j][2], d[i][j][3]);
        }
    }
#undef FETCH
}

// ============================================================
// Kernel D: out = relu(sum_z CP[z] + bias)
// ============================================================
__global__ __launch_bounds__(256) void kernelD(
    const float* __restrict__ pb, float* __restrict__ out)
{
    const int idx = blockIdx.x * 256 + threadIdx.x;
    float4 a = make_float4(0.f, 0.f, 0.f, 0.f);
#pragma unroll
    for (int z = 0; z < SPLITK; z++) {
        float4 v = ((const float4*)g_CP)[(size_t)z * (B_ * OUT_ / 4) + idx];
        a.x += v.x; a.y += v.y; a.z += v.z; a.w += v.w;
    }
    float4 bi = ((const float4*)pb)[idx & (OUT_ / 4 - 1)];
    float4 r;
    r.x = fmaxf(a.x + bi.x, 0.f);
    r.y = fmaxf(a.y + bi.y, 0.f);
    r.z = fmaxf(a.z + bi.z, 0.f);
    r.w = fmaxf(a.w + bi.w, 0.f);
    ((float4*)out)[idx] = r;
}

extern "C" void kernel_launch(void* const* d_in, const int* in_sizes, int n_in,
                              void* d_out, int out_size)
{
    const float* stat = (const float*)d_in[0];
    const float* asr  = (const float*)d_in[1];
    const float* mmv  = (const float*)d_in[2];
    const float* w1   = (const float*)d_in[3];
    const float* b1   = (const float*)d_in[4];
    const float* w2   = (const float*)d_in[5];
    const float* b2   = (const float*)d_in[6];
    const float* tau  = (const float*)d_in[7];
    const float* emb  = (const float*)d_in[8];
    const float* pw   = (const float*)d_in[9];
    const float* pb   = (const float*)d_in[10];
    float* out = (float*)d_out;

    static int smem_set = 0;
    if (!smem_set) {
        cudaFuncSetAttribute(kernelC, cudaFuncAttributeMaxDynamicSharedMemorySize, SMEM_C_BYTES);
        smem_set = 1;
    }

    kernelTZ<<<2816, 256>>>(stat, asr, mmv);                      // 1st
    kernelAB<<<1024 + 112, 256>>>(w1, b1, w2, b2, tau, emb, pw);  // 2nd
    dim3 gc(B_ / 128, OUT_ / 128, SPLITK);
    kernelC<<<gc, 256, SMEM_C_BYTES>>>();                         // 3rd
    kernelD<<<(B_ * OUT_ / 4) / 256, 256>>>(pb, out);             // 4th <- profiled
}